// round 13
// baseline (speedup 1.0000x reference)
#include <cuda_runtime.h>
#include <cuda_fp16.h>
#include <math.h>
#include <stdint.h>

// Problem constants: N=20000, E=640000, S=128, V=16, E_DIM=32
#define MAXN 20000

__device__ float g_agg_s[MAXN * 128];
__device__ float g_agg_v[MAXN * 48];

// Per-node precomputed: Y1 = s @ msgW1[0:128], Y2 = s @ msgW1[128:256],
//                       Z  = s @ updW1[0:128]
__device__ float g_Y1[MAXN * 128];
__device__ float g_Y2[MAXN * 128];
__device__ float g_Z[MAXN * 128];
// Per-node vector norms and v-projection partials
__device__ float g_vn[MAXN * 16];
__device__ float g_VA[MAXN * 48];   // v @ msgWv[0:16]   (src role)
__device__ float g_VB[MAXN * 48];   // v @ msgWv[16:32]  (dst role)
__device__ float g_UVA[MAXN * 48];  // v @ updWv[0:16]

// Pre-converted fp16 hi/lo weights (row-major [k][n]).
__device__ __half g_W1ahi[128 * 128];  // msg W1 rows 0..127
__device__ __half g_W1alo[128 * 128];
__device__ __half g_W1bhi[128 * 128];  // msg W1 rows 128..255
__device__ __half g_W1blo[128 * 128];
__device__ __half g_W1phi[80 * 128];   // msg W1 rows 256..321, padded to 80
__device__ __half g_W1plo[80 * 128];
__device__ __half g_W2hi[128 * 128];
__device__ __half g_W2lo[128 * 128];
__device__ __half g_Wgphi[128 * 16];   // msg W2 @ Wg (fused gate)
__device__ __half g_Wgplo[128 * 16];
__device__ float  g_bgp[16];           // msg b2 @ Wg + bg
__device__ __half g_U1ahi[128 * 128];  // upd W1 rows 0..127
__device__ __half g_U1alo[128 * 128];

__device__ __forceinline__ float sigmoidf_(float x) {
    return 1.0f / (1.0f + __expf(-x));
}
__device__ __forceinline__ uint32_t smem_to_u32(const void* p) {
    uint32_t a;
    asm("{ .reg .u64 t; cvta.to.shared.u64 t, %1; cvt.u32.u64 %0, t; }"
        : "=r"(a) : "l"(p));
    return a;
}
__device__ __forceinline__ void ldsm4(uint32_t addr, uint32_t* r) {
    asm volatile("ldmatrix.sync.aligned.m8n8.x4.shared.b16 {%0,%1,%2,%3}, [%4];"
        : "=r"(r[0]), "=r"(r[1]), "=r"(r[2]), "=r"(r[3]) : "r"(addr));
}
__device__ __forceinline__ void ldsm4t(uint32_t addr, uint32_t* r) {
    asm volatile("ldmatrix.sync.aligned.m8n8.x4.trans.shared.b16 {%0,%1,%2,%3}, [%4];"
        : "=r"(r[0]), "=r"(r[1]), "=r"(r[2]), "=r"(r[3]) : "r"(addr));
}
__device__ __forceinline__ void mma_f16(float* c, const uint32_t* a, const uint32_t* b) {
    asm volatile(
        "mma.sync.aligned.m16n8k16.row.col.f32.f16.f16.f32 "
        "{%0,%1,%2,%3}, {%4,%5,%6,%7}, {%8,%9}, {%0,%1,%2,%3};"
        : "+f"(c[0]), "+f"(c[1]), "+f"(c[2]), "+f"(c[3])
        : "r"(a[0]), "r"(a[1]), "r"(a[2]), "r"(a[3]), "r"(b[0]), "r"(b[1]));
}
__device__ __forceinline__ uint32_t pack_h2(float x0, float x1) {
    __half2 t = __floats2half2_rn(x0, x1);
    return *(uint32_t*)&t;
}
__device__ __forceinline__ void red4(float* p, float a, float b, float c, float d) {
    asm volatile("red.global.add.v4.f32 [%0], {%1, %2, %3, %4};"
        :: "l"(p), "f"(a), "f"(b), "f"(c), "f"(d) : "memory");
}
__device__ __forceinline__ void red2(float* p, float a, float b) {
    asm volatile("red.global.add.v2.f32 [%0], {%1, %2};"
        :: "l"(p), "f"(a), "f"(b) : "memory");
}

// ---------------------------------------------------------------------------
__global__ void zero_kernel(int n) {
    int total = n * 176;
    for (int i = blockIdx.x * blockDim.x + threadIdx.x; i < total;
         i += gridDim.x * blockDim.x) {
        if (i < n * 128) g_agg_s[i] = 0.0f;
        else             g_agg_v[i - n * 128] = 0.0f;
    }
}

// One-time weight conversion / fusion.
__global__ void prep_weights(const float* __restrict__ W1,
                             const float* __restrict__ W2,
                             const float* __restrict__ b2,
                             const float* __restrict__ Wg,
                             const float* __restrict__ bg,
                             const float* __restrict__ uW1) {
    int i = blockIdx.x * blockDim.x + threadIdx.x;
    if (i < 80 * 128) {
        int k = i >> 7;
        float val = (k < 66) ? W1[(256 + k) * 128 + (i & 127)] : 0.0f;
        __half h = __float2half_rn(val);
        g_W1phi[i] = h;
        g_W1plo[i] = __float2half_rn(val - __half2float(h));
    } else if (i < 26624) {
        int j = i - 10240;
        float val = W1[j];
        __half h = __float2half_rn(val);
        g_W1ahi[j] = h;
        g_W1alo[j] = __float2half_rn(val - __half2float(h));
    } else if (i < 43008) {
        int j = i - 26624;
        float val = W1[128 * 128 + j];
        __half h = __float2half_rn(val);
        g_W1bhi[j] = h;
        g_W1blo[j] = __float2half_rn(val - __half2float(h));
    } else if (i < 59392) {
        int j = i - 43008;
        float val = W2[j];
        __half h = __float2half_rn(val);
        g_W2hi[j] = h;
        g_W2lo[j] = __float2half_rn(val - __half2float(h));
    } else if (i < 61440) {
        int j = i - 59392;
        int k = j >> 4, w = j & 15;
        float a = 0.0f;
        for (int c = 0; c < 128; ++c)
            a = fmaf(W2[k * 128 + c], Wg[c * 16 + w], a);
        __half h = __float2half_rn(a);
        g_Wgphi[j] = h;
        g_Wgplo[j] = __float2half_rn(a - __half2float(h));
    } else if (i < 61456) {
        int w = i - 61440;
        float a = bg[w];
        for (int c = 0; c < 128; ++c)
            a = fmaf(b2[c], Wg[c * 16 + w], a);
        g_bgp[w] = a;
    } else if (i < 77840) {
        int j = i - 61456;
        float val = uW1[j];  // upd W1 rows 0..127
        __half h = __float2half_rn(val);
        g_U1ahi[j] = h;
        g_U1alo[j] = __float2half_rn(val - __half2float(h));
    }
}

// ---------------------------------------------------------------------------
// Per-node prep: vector norms + v-projection partials.
// VA = v@msgWv[0:16], VB = v@msgWv[16:32], UVA = v@updWv[0:16]. 32 nodes/CTA.
// ---------------------------------------------------------------------------
__global__ __launch_bounds__(256) void prep_nodes(const float* __restrict__ v,
                                                  const float* __restrict__ Wv,
                                                  const float* __restrict__ uWv,
                                                  int n) {
    __shared__ float sv[32 * 48];
    __shared__ float sw[528];
    __shared__ float swu[256];   // upd Wv rows 0..15
    const int tid = threadIdx.x;
    const int n0 = blockIdx.x * 32;

    for (int q = tid; q < 32 * 48; q += 256) {
        int i = q / 48, k = q - i * 48;
        int nd = min(n0 + i, n - 1);
        sv[q] = v[(size_t)nd * 48 + k];
    }
    for (int q = tid; q < 528; q += 256) sw[q] = Wv[q];
    for (int q = tid; q < 256; q += 256) swu[q] = uWv[q];
    __syncthreads();

    for (int q = tid; q < 32 * 16; q += 256) {
        int i = q >> 4, j = q & 15;
        if (n0 + i >= n) continue;
        float a = sv[i * 48 + j * 3], b = sv[i * 48 + j * 3 + 1],
              c = sv[i * 48 + j * 3 + 2];
        g_vn[(size_t)(n0 + i) * 16 + j] = sqrtf(fmaxf(a * a + b * b + c * c, 1e-8f));
    }
    for (int q = tid; q < 32 * 48; q += 256) {
        int i = q / 48, r = q - i * 48;
        if (n0 + i >= n) continue;
        int w = r / 3, c = r - w * 3;
        float a = 0.0f, b = 0.0f, u = 0.0f;
#pragma unroll
        for (int j = 0; j < 16; ++j) {
            float vv = sv[i * 48 + j * 3 + c];
            a = fmaf(vv, sw[j * 16 + w], a);
            b = fmaf(vv, sw[(16 + j) * 16 + w], b);
            u = fmaf(vv, swu[j * 16 + w], u);
        }
        g_VA[(size_t)(n0 + i) * 48 + r] = a;
        g_VB[(size_t)(n0 + i) * 48 + r] = b;
        g_UVA[(size_t)(n0 + i) * 48 + r] = u;
    }
}

// ---------------------------------------------------------------------------
// Y kernel: per-node partials (fp16 2-term, mma). blockIdx.y selects output:
// 0: Y1 = s@msgW1a, 1: Y2 = s@msgW1b, 2: Z = s@updW1a.
// ---------------------------------------------------------------------------
__global__ __launch_bounds__(256) void y_kernel(const float* __restrict__ s, int n) {
    __shared__ __align__(16) char ysm[6144 + 8704];
    const uint32_t smb = smem_to_u32(ysm);
    const int tid = threadIdx.x;
    const int lane = tid & 31;
    const int wid = tid >> 5;
    const int n0 = blockIdx.x * 128;

    const __half* Whi;
    const __half* Wlo;
    float* Y;
    if (blockIdx.y == 0)      { Whi = g_W1ahi; Wlo = g_W1alo; Y = g_Y1; }
    else if (blockIdx.y == 1) { Whi = g_W1bhi; Wlo = g_W1blo; Y = g_Y2; }
    else                      { Whi = g_U1ahi; Wlo = g_U1alo; Y = g_Z; }

    const int mw = (wid & 3) * 32;
    const int nw = (wid >> 2) * 64;
    const int arow = lane & 15;
    const int acol = lane >> 4;

    float acc[2][8][4];
#pragma unroll
    for (int mt = 0; mt < 2; ++mt)
#pragma unroll
        for (int nt = 0; nt < 8; ++nt)
#pragma unroll
            for (int r = 0; r < 4; ++r) acc[mt][nt][r] = 0.0f;

    for (int kt = 0; kt < 8; ++kt) {
        for (int q = tid; q < 2048; q += 256) {
            int e = q >> 4, kk = q & 15;
            int nd = min(n0 + e, n - 1);
            *(__half*)(ysm + e * 48 + kk * 2) =
                __float2half_rn(s[nd * 128 + kt * 16 + kk]);
        }
        for (int q = tid; q < 2048; q += 256) {
            int kk = q >> 7, nc = q & 127;
            *(__half*)(ysm + 6144 + kk * 272 + nc * 2) = Whi[(kt * 16 + kk) * 128 + nc];
            *(__half*)(ysm + 6144 + 4352 + kk * 272 + nc * 2) = Wlo[(kt * 16 + kk) * 128 + nc];
        }
        __syncthreads();
        uint32_t ah[2][4];
#pragma unroll
        for (int mt = 0; mt < 2; ++mt)
            ldsm4(smb + (mw + 16 * mt + arow) * 48 + acol * 16, ah[mt]);
#pragma unroll
        for (int nb = 0; nb < 4; ++nb) {
            uint32_t bh[4], bl[4];
            uint32_t baddr = smb + 6144 + arow * 272 + (nw + nb * 16 + acol * 8) * 2;
            ldsm4t(baddr, bh);
            ldsm4t(baddr + 4352, bl);
#pragma unroll
            for (int mt = 0; mt < 2; ++mt) {
                mma_f16(acc[mt][2 * nb],     ah[mt], bh);
                mma_f16(acc[mt][2 * nb + 1], ah[mt], bh + 2);
                mma_f16(acc[mt][2 * nb],     ah[mt], bl);
                mma_f16(acc[mt][2 * nb + 1], ah[mt], bl + 2);
            }
        }
        __syncthreads();
    }
#pragma unroll
    for (int mt = 0; mt < 2; ++mt) {
        int r0 = mw + 16 * mt + (lane >> 2);
#pragma unroll
        for (int nt = 0; nt < 8; ++nt) {
            int nc = nw + nt * 8 + (lane & 3) * 2;
            if (n0 + r0 < n) {
                float2 u = make_float2(acc[mt][nt][0], acc[mt][nt][1]);
                *(float2*)&Y[(size_t)(n0 + r0) * 128 + nc] = u;
            }
            if (n0 + r0 + 8 < n) {
                float2 u = make_float2(acc[mt][nt][2], acc[mt][nt][3]);
                *(float2*)&Y[(size_t)(n0 + r0 + 8) * 128 + nc] = u;
            }
        }
    }
}

// ===========================================================================
// Edge kernel: 128 edges/CTA, 256 threads.
// GEMM1 K=80 (node parts in Y1/Y2 acc init); gate fused into GEMM2.
// m_s scattered directly from registers via red.v2 (no sms staging).
// smem byte map (total 106624), lifetimes as r11 (sms region now unused):
//   T @0 (34816), X dbl @34816, sev @67584, snorm @69632 (GEMM1) then
//   Wgp @69632 / sg @79936, wv32 @88128, W dbl @88192, idx @105600.
// ===========================================================================
#define OB_T     0
#define OB_X     34816
#define OB_SEV   67584
#define OB_NORM  69632
#define OB_WGP   69632
#define OB_WGPLO 73728
#define OB_SG    79936
#define OB_WV32  88128
#define OB_W     88192
#define OB_SRC   105600
#define OB_DST   106112
#define EDGE_SMEM_BYTES 106624
#define XBUF(b)  (OB_X + (b) * 6144)
#define WBUF(b)  (OB_W + (b) * 8704)
#define WLO_OFF  4352

// edge-local X: k 0..31 edge_s, 32 edge_len, 33..65 vn (src16,dst16,|ev|), 66..79 zero
__device__ __forceinline__ float fetch_x80(int k, int e, int eg,
    const float* __restrict__ es, const float* snorm)
{
    if (k < 32)   return es[eg * 32 + k];
    if (k == 32)  return snorm[e * 36 + 32];
    if (k < 66)   return snorm[e * 36 + (k - 33)];
    return 0.0f;
}

__global__ __launch_bounds__(256, 2) void edge_kernel(
    const int* __restrict__ ei, const float* __restrict__ es,
    const float* __restrict__ ev,
    const float* __restrict__ b1, const float* __restrict__ b2,
    const float* __restrict__ Wv, int E)
{
    extern __shared__ __align__(16) char smraw[];
    float* smf = (float*)smraw;
    const uint32_t smb = smem_to_u32(smraw);

    const int tid = threadIdx.x;
    const int lane = tid & 31;
    const int wid = tid >> 5;
    const int e0 = blockIdx.x * 128;
    const int nval = min(128, E - e0);

    int* ssrc = (int*)(smraw + OB_SRC);
    int* sdst = (int*)(smraw + OB_DST);
    float* snorm = (float*)(smraw + OB_NORM);

    // ---- phase 1: indices, vn staging, ev ----
    if (tid < 128) {
        int ee = e0 + min(tid, nval - 1);
        ssrc[tid] = ei[ee];
        sdst[tid] = ei[E + ee];
    }
    if (tid >= 240) {
        smf[OB_WV32 / 4 + (tid - 240)] = Wv[32 * 16 + (tid - 240)];
    }
    __syncthreads();
    for (int q = tid; q < 1024; q += 256) {
        int e = q >> 3, p = q & 7;
        float4 t = (p < 4)
            ? *(const float4*)&g_vn[(size_t)ssrc[e] * 16 + p * 4]
            : *(const float4*)&g_vn[(size_t)sdst[e] * 16 + (p - 4) * 4];
        *(float4*)&snorm[e * 36 + (p < 4 ? p * 4 : 16 + (p - 4) * 4)] = t;
    }
    if (tid < 128) {
        int eg = e0 + min(tid, nval - 1);
        float a = ev[eg * 3], b = ev[eg * 3 + 1], c = ev[eg * 3 + 2];
        float nn = sqrtf(fmaxf(a * a + b * b + c * c, 1e-8f));
        snorm[tid * 36 + 32] = nn;
        float* se = smf + OB_SEV / 4 + tid * 4;
        se[0] = a; se[1] = b; se[2] = c; se[3] = nn;
    }
    __syncthreads();

    const int mw = (wid & 3) * 32;
    const int nw = (wid >> 2) * 64;
    const int arow = lane & 15;
    const int acol = lane >> 4;

    const int xe_base = tid >> 3;
    const int xk2 = (tid & 7) * 2;
    const int wkk = tid >> 4;
    const int wn8 = (tid & 15) * 8;

    float acc[2][8][4];

    // ---- acc init: Y1[src] + Y2[dst] fragments ----
    {
        const int rbase = mw + (lane >> 2);
        const int cbase = nw + (lane & 3) * 2;
#pragma unroll
        for (int mt = 0; mt < 2; ++mt) {
#pragma unroll
            for (int rh = 0; rh < 2; ++rh) {
                int r = rbase + 16 * mt + 8 * rh;
                const float* y1 = g_Y1 + (size_t)ssrc[r] * 128;
                const float* y2 = g_Y2 + (size_t)sdst[r] * 128;
#pragma unroll
                for (int nt = 0; nt < 8; ++nt) {
                    int nc = cbase + nt * 8;
                    float2 a = *(const float2*)&y1[nc];
                    float2 b = *(const float2*)&y2[nc];
                    acc[mt][nt][2 * rh]     = a.x + b.x;
                    acc[mt][nt][2 * rh + 1] = a.y + b.y;
                }
            }
        }
    }

    float xr[4][2];
    uint4 wh, wl;

    // ---- prologue: tile 0 ----
    {
#pragma unroll
        for (int it = 0; it < 4; ++it) {
            int e = xe_base + it * 32;
            int eg = e0 + min(e, nval - 1);
            xr[it][0] = fetch_x80(xk2,     e, eg, es, snorm);
            xr[it][1] = fetch_x80(xk2 + 1, e, eg, es, snorm);
        }
        wh = *(const uint4*)&g_W1phi[wkk * 128 + wn8];
        wl = *(const uint4*)&g_W1plo[wkk * 128 + wn8];
#pragma unroll
        for (int it = 0; it < 4; ++it) {
            int e = xe_base + it * 32;
            *(uint32_t*)(smraw + XBUF(0) + e * 48 + xk2 * 2) =
                pack_h2(xr[it][0], xr[it][1]);
        }
        *(uint4*)(smraw + WBUF(0) + wkk * 272 + wn8 * 2) = wh;
        *(uint4*)(smraw + WBUF(0) + WLO_OFF + wkk * 272 + wn8 * 2) = wl;
    }
    __syncthreads();

    // ================= GEMM1: edge-local part, K=80 (5 tiles) ================
    for (int kt = 0; kt < 5; ++kt) {
        const int cur = kt & 1, nxt = cur ^ 1;
        const bool more = (kt + 1 < 5);
        if (more) {
            int kbase = (kt + 1) * 16;
#pragma unroll
            for (int it = 0; it < 4; ++it) {
                int e = xe_base + it * 32;
                int eg = e0 + min(e, nval - 1);
                xr[it][0] = fetch_x80(kbase + xk2,     e, eg, es, snorm);
                xr[it][1] = fetch_x80(kbase + xk2 + 1, e, eg, es, snorm);
            }
            wh = *(const uint4*)&g_W1phi[(kbase + wkk) * 128 + wn8];
            wl = *(const uint4*)&g_W1plo[(kbase + wkk) * 128 + wn8];
        }
        {
            uint32_t ah[2][4];
#pragma unroll
            for (int mt = 0; mt < 2; ++mt)
                ldsm4(smb + XBUF(cur) + (mw + 16 * mt + arow) * 48 + acol * 16, ah[mt]);
#pragma unroll
            for (int nb = 0; nb < 4; ++nb) {
                uint32_t bh[4], bl[4];
                uint32_t baddr = smb + WBUF(cur) + arow * 272 + (nw + nb * 16 + acol * 8) * 2;
                ldsm4t(baddr, bh);
                ldsm4t(baddr + WLO_OFF, bl);
#pragma unroll
                for (int mt = 0; mt < 2; ++mt) {
                    mma_f16(acc[mt][2 * nb],     ah[mt], bh);
                    mma_f16(acc[mt][2 * nb + 1], ah[mt], bh + 2);
                    mma_f16(acc[mt][2 * nb],     ah[mt], bl);
                    mma_f16(acc[mt][2 * nb + 1], ah[mt], bl + 2);
                }
            }
        }
        if (more) {
#pragma unroll
            for (int it = 0; it < 4; ++it) {
                int e = xe_base + it * 32;
                *(uint32_t*)(smraw + XBUF(nxt) + e * 48 + xk2 * 2) =
                    pack_h2(xr[it][0], xr[it][1]);
            }
            *(uint4*)(smraw + WBUF(nxt) + wkk * 272 + wn8 * 2) = wh;
            *(uint4*)(smraw + WBUF(nxt) + WLO_OFF + wkk * 272 + wn8 * 2) = wl;
        }
        __syncthreads();
    }

    // ---- epilogue 1: +b1, silu -> T fp16 ----
#pragma unroll
    for (int mt = 0; mt < 2; ++mt) {
        int r0 = mw + 16 * mt + (lane >> 2);
#pragma unroll
        for (int nt = 0; nt < 8; ++nt) {
            int n = nw + nt * 8 + (lane & 3) * 2;
            float2 bb = *(const float2*)&b1[n];
            float h0 = acc[mt][nt][0] + bb.x, h1 = acc[mt][nt][1] + bb.y;
            float h2 = acc[mt][nt][2] + bb.x, h3 = acc[mt][nt][3] + bb.y;
            float t0 = h0 * sigmoidf_(h0), t1 = h1 * sigmoidf_(h1);
            float t2 = h2 * sigmoidf_(h2), t3 = h3 * sigmoidf_(h3);
            *(uint32_t*)(smraw + OB_T + r0 * 272 + n * 2)       = pack_h2(t0, t1);
            *(uint32_t*)(smraw + OB_T + (r0 + 8) * 272 + n * 2) = pack_h2(t2, t3);
        }
    }
    __syncthreads();

    // stage Wgp hi/lo (norm region dead after GEMM1)
    for (int q = tid; q < 1024; q += 256) {
        ((uint32_t*)(smraw + OB_WGP))[q]   = ((const uint32_t*)g_Wgphi)[q];
        ((uint32_t*)(smraw + OB_WGPLO))[q] = ((const uint32_t*)g_Wgplo)[q];
    }

    // ================= GEMM2: m_s = T @ W2 (K=128) + fused gate ==============
    float gacc[2][2][4];
#pragma unroll
    for (int mt = 0; mt < 2; ++mt) {
#pragma unroll
        for (int nt = 0; nt < 8; ++nt)
#pragma unroll
            for (int r = 0; r < 4; ++r) acc[mt][nt][r] = 0.0f;
#pragma unroll
        for (int gn = 0; gn < 2; ++gn)
#pragma unroll
            for (int r = 0; r < 4; ++r) gacc[mt][gn][r] = 0.0f;
    }

    wh = *(const uint4*)&g_W2hi[wkk * 128 + wn8];
    wl = *(const uint4*)&g_W2lo[wkk * 128 + wn8];
    *(uint4*)(smraw + WBUF(0) + wkk * 272 + wn8 * 2) = wh;
    *(uint4*)(smraw + WBUF(0) + WLO_OFF + wkk * 272 + wn8 * 2) = wl;
    __syncthreads();

    for (int kt = 0; kt < 8; ++kt) {
        const int cur = kt & 1, nxt = cur ^ 1;
        const bool more = (kt + 1 < 8);
        if (more) {
            wh = *(const uint4*)&g_W2hi[((kt + 1) * 16 + wkk) * 128 + wn8];
            wl = *(const uint4*)&g_W2lo[((kt + 1) * 16 + wkk) * 128 + wn8];
        }
        {
            uint32_t ah[2][4];
#pragma unroll
            for (int mt = 0; mt < 2; ++mt)
                ldsm4(smb + OB_T + (mw + 16 * mt + arow) * 272 + (kt * 16 + acol * 8) * 2,
                      ah[mt]);
#pragma unroll
            for (int nb = 0; nb < 4; ++nb) {
                uint32_t bh[4], bl[4];
                uint32_t baddr = smb + WBUF(cur) + arow * 272 + (nw + nb * 16 + acol * 8) * 2;
                ldsm4t(baddr, bh);
                ldsm4t(baddr + WLO_OFF, bl);
#pragma unroll
                for (int mt = 0; mt < 2; ++mt) {
                    mma_f16(acc[mt][2 * nb],     ah[mt], bh);
                    mma_f16(acc[mt][2 * nb + 1], ah[mt], bh + 2);
                    mma_f16(acc[mt][2 * nb],     ah[mt], bl);
                    mma_f16(acc[mt][2 * nb + 1], ah[mt], bl + 2);
                }
            }
            // fused gate: 16 extra N columns
            {
                uint32_t gh[4], gl[4];
                uint32_t gaddr = smb + OB_WGP + kt * 512 + arow * 32 + acol * 16;
                ldsm4t(gaddr, gh);
                ldsm4t(gaddr + (OB_WGPLO - OB_WGP), gl);
#pragma unroll
                for (int mt = 0; mt < 2; ++mt) {
                    mma_f16(gacc[mt][0], ah[mt], gh);
                    mma_f16(gacc[mt][1], ah[mt], gh + 2);
                    mma_f16(gacc[mt][0], ah[mt], gl);
                    mma_f16(gacc[mt][1], ah[mt], gl + 2);
                }
            }
        }
        if (more) {
            *(uint4*)(smraw + WBUF(nxt) + wkk * 272 + wn8 * 2) = wh;
            *(uint4*)(smraw + WBUF(nxt) + WLO_OFF + wkk * 272 + wn8 * 2) = wl;
        }
        __syncthreads();
    }

    // ---- epilogue 2: direct red.v2 scatter of m_s (+b2); gate sigmoid -> sg
    float* sg = smf + OB_SG / 4;  // [128][16]
#pragma unroll
    for (int mt = 0; mt < 2; ++mt) {
        int r0 = mw + 16 * mt + (lane >> 2);
        int r1 = r0 + 8;
        float* d0 = &g_agg_s[(size_t)sdst[r0] * 128];
        float* d1 = &g_agg_s[(size_t)sdst[r1] * 128];
        bool v0 = (r0 < nval), v1 = (r1 < nval);
#pragma unroll
        for (int nt = 0; nt < 8; ++nt) {
            int n = nw + nt * 8 + (lane & 3) * 2;
            float2 bb = *(const float2*)&b2[n];
            if (v0) red2(d0 + n, acc[mt][nt][0] + bb.x, acc[mt][nt][1] + bb.y);
            if (v1) red2(d1 + n, acc[mt][nt][2] + bb.x, acc[mt][nt][3] + bb.y);
        }
#pragma unroll
        for (int gn = 0; gn < 2; ++gn) {
            int col = gn * 8 + (lane & 3) * 2;
            float b0 = g_bgp[col], b1g = g_bgp[col + 1];
            sg[r0 * 16 + col]       = sigmoidf_(gacc[mt][gn][0] + b0);
            sg[r0 * 16 + col + 1]   = sigmoidf_(gacc[mt][gn][1] + b1g);
            sg[r1 * 16 + col]       = sigmoidf_(gacc[mt][gn][2] + b0);
            sg[r1 * 16 + col + 1]   = sigmoidf_(gacc[mt][gn][3] + b1g);
        }
    }
    __syncthreads();

    // ---- v projection via precomputed VA/VB, scatter-add ----
    for (int q = tid; q < 1536; q += 256) {
        int e = q / 12, rq = q - e * 12;
        if (e >= nval) continue;
        float4 a4 = *(const float4*)&g_VA[(size_t)ssrc[e] * 48 + rq * 4];
        float4 b4 = *(const float4*)&g_VB[(size_t)sdst[e] * 48 + rq * 4];
        float av[4] = {a4.x + b4.x, a4.y + b4.y, a4.z + b4.z, a4.w + b4.w};
        float out[4];
#pragma unroll
        for (int u = 0; u < 4; ++u) {
            int r = rq * 4 + u, w = r / 3, c3 = r - w * 3;
            float val = av[u] + smf[OB_SEV / 4 + e * 4 + c3] * smf[OB_WV32 / 4 + w];
            out[u] = val * sg[e * 16 + w];
        }
        red4(&g_agg_v[(size_t)sdst[e] * 48 + rq * 4], out[0], out[1], out[2], out[3]);
    }
}

// ---------------------------------------------------------------------------
// Node update kernel: hoisted Z (= s@uW1a), g_vn reuse, UVA for v-projection.
// First GEMV K reduced 288 -> 160 (agg_s 128 + norms 32).
// ---------------------------------------------------------------------------
__global__ __launch_bounds__(128) void node_kernel(
    const float* __restrict__ s, const float* __restrict__ v,
    const float* __restrict__ W1, const float* __restrict__ b1,
    const float* __restrict__ W2, const float* __restrict__ b2,
    const float* __restrict__ Wv, const float* __restrict__ Wg,
    const float* __restrict__ bg, const float* __restrict__ lng,
    const float* __restrict__ lnb,
    float* __restrict__ out_s, float* __restrict__ out_v, int n)
{
    __shared__ float xu[8][164];
    __shared__ float vinB[8][48];
    __shared__ float tt[8][128];
    __shared__ float dsm[8][132];
    __shared__ float gate[8][16];
    __shared__ float rsum[8][4], rsq[8][4];

    const int tid = threadIdx.x;
    const int n0 = blockIdx.x * 8;

    // xu: k 0..127 = agg_s, 128..143 = v norms (g_vn), 144..159 = agg_v norms
    for (int idx = tid; idx < 8 * 144; idx += 128) {
        int i = idx / 144, k = idx - i * 144;
        int nd = min(n0 + i, n - 1);
        xu[i][k] = (k < 128) ? g_agg_s[(size_t)nd * 128 + k]
                             : g_vn[(size_t)nd * 16 + (k - 128)];
    }
    for (int idx = tid; idx < 8 * 48; idx += 128) {
        int i = idx / 48, k = idx - i * 48;
        int nd = min(n0 + i, n - 1);
        vinB[i][k] = g_agg_v[(size_t)nd * 48 + k];
    }
    __syncthreads();
    for (int idx = tid; idx < 8 * 16; idx += 128) {
        int i = idx >> 4, j = idx & 15;
        float a = vinB[i][j * 3], b = vinB[i][j * 3 + 1], c = vinB[i][j * 3 + 2];
        xu[i][144 + j] = sqrtf(fmaxf(a * a + b * b + c * c, 1e-8f));
    }
    __syncthreads();

    const int c = tid;
    float acc[8];
    {
        float bb = b1[c];
#pragma unroll
        for (int i = 0; i < 8; ++i) {
            int nd = min(n0 + i, n - 1);
            acc[i] = g_Z[(size_t)nd * 128 + c] + bb;
        }
    }
    for (int k = 0; k < 160; ++k) {
        float w = W1[(128 + k) * 128 + c];
#pragma unroll
        for (int i = 0; i < 8; ++i) acc[i] = fmaf(xu[i][k], w, acc[i]);
    }
#pragma unroll
    for (int i = 0; i < 8; ++i) {
        float h = acc[i];
        tt[i][c] = h * sigmoidf_(h);
    }
    __syncthreads();

    float acc2[8];
    {
        float bb = b2[c];
#pragma unroll
        for (int i = 0; i < 8; ++i) acc2[i] = bb;
    }
    for (int k = 0; k < 128; ++k) {
        float w = W2[k * 128 + c];
#pragma unroll
        for (int i = 0; i < 8; ++i) acc2[i] = fmaf(tt[i][k], w, acc2[i]);
    }
#pragma unroll
    for (int i = 0; i < 8; ++i) dsm[i][c] = acc2[i];
    __syncthreads();

    {
        int i = tid >> 4, w = tid & 15;
        float g = bg[w];
        for (int cc = 0; cc < 128; ++cc)
            g = fmaf(dsm[i][cc], Wg[cc * 16 + w], g);
        gate[i][w] = sigmoidf_(g);
    }

    float val[8];
#pragma unroll
    for (int i = 0; i < 8; ++i) {
        int nd = min(n0 + i, n - 1);
        val[i] = s[nd * 128 + c] + acc2[i];
    }
    const int lane = tid & 31, wq = tid >> 5;
    float psum[8], psq[8];
#pragma unroll
    for (int i = 0; i < 8; ++i) { psum[i] = val[i]; psq[i] = val[i] * val[i]; }
#pragma unroll
    for (int off = 16; off > 0; off >>= 1) {
#pragma unroll
        for (int i = 0; i < 8; ++i) {
            psum[i] += __shfl_xor_sync(0xffffffffu, psum[i], off);
            psq[i]  += __shfl_xor_sync(0xffffffffu, psq[i],  off);
        }
    }
    if (lane == 0) {
#pragma unroll
        for (int i = 0; i < 8; ++i) { rsum[i][wq] = psum[i]; rsq[i][wq] = psq[i]; }
    }
    __syncthreads();

#pragma unroll
    for (int i = 0; i < 8; ++i) {
        if (n0 + i >= n) continue;
        float sum = rsum[i][0] + rsum[i][1] + rsum[i][2] + rsum[i][3];
        float sq  = rsq[i][0] + rsq[i][1] + rsq[i][2] + rsq[i][3];
        float mu  = sum * (1.0f / 128.0f);
        float var = sq * (1.0f / 128.0f) - mu * mu;
        float o = (val[i] - mu) * rsqrtf(var + 1e-5f) * lng[c] + lnb[c];
        out_s[(n0 + i) * 128 + c] = o;
    }

    for (int q = tid; q < 8 * 48; q += 128) {
        int i = q / 48, r = q - i * 48;
        if (n0 + i >= n) continue;
        int w = r / 3, cc = r - w * 3;
        float a = g_UVA[(size_t)(n0 + i) * 48 + r];
#pragma unroll
        for (int j = 0; j < 16; ++j)
            a = fmaf(vinB[i][j * 3 + cc], Wv[(16 + j) * 16 + w], a);
        a *= gate[i][w];
        out_v[(n0 + i) * 48 + r] = v[(n0 + i) * 48 + r] + a;
    }
}

// ---------------------------------------------------------------------------
extern "C" void kernel_launch(void* const* d_in, const int* in_sizes, int n_in,
                              void* d_out, int out_size)
{
    const float* s   = (const float*)d_in[0];
    const float* v   = (const float*)d_in[1];
    const int*   ei  = (const int*)  d_in[2];
    const float* es  = (const float*)d_in[3];
    const float* ev  = (const float*)d_in[4];
    const float* mW1 = (const float*)d_in[5];
    const float* mb1 = (const float*)d_in[6];
    const float* mW2 = (const float*)d_in[7];
    const float* mb2 = (const float*)d_in[8];
    const float* mWv = (const float*)d_in[9];
    const float* mWg = (const float*)d_in[10];
    const float* mbg = (const float*)d_in[11];
    const float* uW1 = (const float*)d_in[12];
    const float* ub1 = (const float*)d_in[13];
    const float* uW2 = (const float*)d_in[14];
    const float* ub2 = (const float*)d_in[15];
    const float* uWv = (const float*)d_in[16];
    const float* uWg = (const float*)d_in[17];
    const float* ubg = (const float*)d_in[18];
    const float* lng = (const float*)d_in[19];
    const float* lnb = (const float*)d_in[20];

    const int n = in_sizes[0] / 128;
    const int E = in_sizes[2] / 2;

    float* out_s = (float*)d_out;
    float* out_v = out_s + (size_t)n * 128;

    cudaFuncSetAttribute(edge_kernel,
                         cudaFuncAttributeMaxDynamicSharedMemorySize,
                         EDGE_SMEM_BYTES);

    zero_kernel<<<(n * 176 + 255) / 256, 256>>>(n);
    prep_weights<<<(77840 + 255) / 256, 256>>>(mW1, mW2, mb2, mWg, mbg, uW1);
    prep_nodes<<<(n + 31) / 32, 256>>>(v, mWv, uWv, n);
    y_kernel<<<dim3((n + 127) / 128, 3), 256>>>(s, n);

    edge_kernel<<<(E + 127) / 128, 256, EDGE_SMEM_BYTES>>>(
        ei, es, ev, mb1, mb2, mWv, E);

    node_kernel<<<(n + 7) / 8, 128>>>(
        s, v, uW1, ub1, uW2, ub2, uWv, uWg, ubg, lng, lnb,
        out_s, out_v, n);
}

// round 14
// speedup vs baseline: 1.1653x; 1.1653x over previous
#include <cuda_runtime.h>
#include <cuda_fp16.h>
#include <math.h>
#include <stdint.h>

// Problem constants: N=20000, E=640000, S=128, V=16, E_DIM=32
#define MAXN 20000

__device__ float g_agg_s[MAXN * 128];
__device__ float g_agg_v[MAXN * 48];

// Per-node precomputed: Y1 = s @ msgW1[0:128], Y2 = s @ msgW1[128:256],
//                       Z  = s @ updW1[0:128]
__device__ float g_Y1[MAXN * 128];
__device__ float g_Y2[MAXN * 128];
__device__ float g_Z[MAXN * 128];
__device__ float g_vn[MAXN * 16];
__device__ float g_VA[MAXN * 48];   // v @ msgWv[0:16]   (src role)
__device__ float g_VB[MAXN * 48];   // v @ msgWv[16:32]  (dst role)
__device__ float g_UVA[MAXN * 48];  // v @ updWv[0:16]

// Pre-converted fp16 hi/lo weights (row-major [k][n]).
__device__ __half g_W1ahi[128 * 128];
__device__ __half g_W1alo[128 * 128];
__device__ __half g_W1bhi[128 * 128];
__device__ __half g_W1blo[128 * 128];
__device__ __half g_W1phi[80 * 128];
__device__ __half g_W1plo[80 * 128];
__device__ __half g_W2hi[128 * 128];
__device__ __half g_W2lo[128 * 128];
__device__ __half g_Wgphi[128 * 16];
__device__ __half g_Wgplo[128 * 16];
__device__ float  g_bgp[16];
__device__ __half g_U1ahi[128 * 128];
__device__ __half g_U1alo[128 * 128];

__device__ __forceinline__ float sigmoidf_(float x) {
    return 1.0f / (1.0f + __expf(-x));
}
__device__ __forceinline__ uint32_t smem_to_u32(const void* p) {
    uint32_t a;
    asm("{ .reg .u64 t; cvta.to.shared.u64 t, %1; cvt.u32.u64 %0, t; }"
        : "=r"(a) : "l"(p));
    return a;
}
__device__ __forceinline__ void ldsm4(uint32_t addr, uint32_t* r) {
    asm volatile("ldmatrix.sync.aligned.m8n8.x4.shared.b16 {%0,%1,%2,%3}, [%4];"
        : "=r"(r[0]), "=r"(r[1]), "=r"(r[2]), "=r"(r[3]) : "r"(addr));
}
__device__ __forceinline__ void ldsm4t(uint32_t addr, uint32_t* r) {
    asm volatile("ldmatrix.sync.aligned.m8n8.x4.trans.shared.b16 {%0,%1,%2,%3}, [%4];"
        : "=r"(r[0]), "=r"(r[1]), "=r"(r[2]), "=r"(r[3]) : "r"(addr));
}
__device__ __forceinline__ void mma_f16(float* c, const uint32_t* a, const uint32_t* b) {
    asm volatile(
        "mma.sync.aligned.m16n8k16.row.col.f32.f16.f16.f32 "
        "{%0,%1,%2,%3}, {%4,%5,%6,%7}, {%8,%9}, {%0,%1,%2,%3};"
        : "+f"(c[0]), "+f"(c[1]), "+f"(c[2]), "+f"(c[3])
        : "r"(a[0]), "r"(a[1]), "r"(a[2]), "r"(a[3]), "r"(b[0]), "r"(b[1]));
}
__device__ __forceinline__ uint32_t pack_h2(float x0, float x1) {
    __half2 t = __floats2half2_rn(x0, x1);
    return *(uint32_t*)&t;
}
__device__ __forceinline__ void red4(float* p, float a, float b, float c, float d) {
    asm volatile("red.global.add.v4.f32 [%0], {%1, %2, %3, %4};"
        :: "l"(p), "f"(a), "f"(b), "f"(c), "f"(d) : "memory");
}
__device__ __forceinline__ void red2(float* p, float a, float b) {
    asm volatile("red.global.add.v2.f32 [%0], {%1, %2};"
        :: "l"(p), "f"(a), "f"(b) : "memory");
}

// ---------------------------------------------------------------------------
__global__ void zero_kernel(int n) {
    int total = n * 176;
    for (int i = blockIdx.x * blockDim.x + threadIdx.x; i < total;
         i += gridDim.x * blockDim.x) {
        if (i < n * 128) g_agg_s[i] = 0.0f;
        else             g_agg_v[i - n * 128] = 0.0f;
    }
}

__global__ void prep_weights(const float* __restrict__ W1,
                             const float* __restrict__ W2,
                             const float* __restrict__ b2,
                             const float* __restrict__ Wg,
                             const float* __restrict__ bg,
                             const float* __restrict__ uW1) {
    int i = blockIdx.x * blockDim.x + threadIdx.x;
    if (i < 80 * 128) {
        int k = i >> 7;
        float val = (k < 66) ? W1[(256 + k) * 128 + (i & 127)] : 0.0f;
        __half h = __float2half_rn(val);
        g_W1phi[i] = h;
        g_W1plo[i] = __float2half_rn(val - __half2float(h));
    } else if (i < 26624) {
        int j = i - 10240;
        float val = W1[j];
        __half h = __float2half_rn(val);
        g_W1ahi[j] = h;
        g_W1alo[j] = __float2half_rn(val - __half2float(h));
    } else if (i < 43008) {
        int j = i - 26624;
        float val = W1[128 * 128 + j];
        __half h = __float2half_rn(val);
        g_W1bhi[j] = h;
        g_W1blo[j] = __float2half_rn(val - __half2float(h));
    } else if (i < 59392) {
        int j = i - 43008;
        float val = W2[j];
        __half h = __float2half_rn(val);
        g_W2hi[j] = h;
        g_W2lo[j] = __float2half_rn(val - __half2float(h));
    } else if (i < 61440) {
        int j = i - 59392;
        int k = j >> 4, w = j & 15;
        float a = 0.0f;
        for (int c = 0; c < 128; ++c)
            a = fmaf(W2[k * 128 + c], Wg[c * 16 + w], a);
        __half h = __float2half_rn(a);
        g_Wgphi[j] = h;
        g_Wgplo[j] = __float2half_rn(a - __half2float(h));
    } else if (i < 61456) {
        int w = i - 61440;
        float a = bg[w];
        for (int c = 0; c < 128; ++c)
            a = fmaf(b2[c], Wg[c * 16 + w], a);
        g_bgp[w] = a;
    } else if (i < 77840) {
        int j = i - 61456;
        float val = uW1[j];
        __half h = __float2half_rn(val);
        g_U1ahi[j] = h;
        g_U1alo[j] = __float2half_rn(val - __half2float(h));
    }
}

// ---------------------------------------------------------------------------
__global__ __launch_bounds__(256) void prep_nodes(const float* __restrict__ v,
                                                  const float* __restrict__ Wv,
                                                  const float* __restrict__ uWv,
                                                  int n) {
    __shared__ float sv[32 * 48];
    __shared__ float sw[528];
    __shared__ float swu[256];
    const int tid = threadIdx.x;
    const int n0 = blockIdx.x * 32;

    for (int q = tid; q < 32 * 48; q += 256) {
        int i = q / 48, k = q - i * 48;
        int nd = min(n0 + i, n - 1);
        sv[q] = v[(size_t)nd * 48 + k];
    }
    for (int q = tid; q < 528; q += 256) sw[q] = Wv[q];
    for (int q = tid; q < 256; q += 256) swu[q] = uWv[q];
    __syncthreads();

    for (int q = tid; q < 32 * 16; q += 256) {
        int i = q >> 4, j = q & 15;
        if (n0 + i >= n) continue;
        float a = sv[i * 48 + j * 3], b = sv[i * 48 + j * 3 + 1],
              c = sv[i * 48 + j * 3 + 2];
        g_vn[(size_t)(n0 + i) * 16 + j] = sqrtf(fmaxf(a * a + b * b + c * c, 1e-8f));
    }
    for (int q = tid; q < 32 * 48; q += 256) {
        int i = q / 48, r = q - i * 48;
        if (n0 + i >= n) continue;
        int w = r / 3, c = r - w * 3;
        float a = 0.0f, b = 0.0f, u = 0.0f;
#pragma unroll
        for (int j = 0; j < 16; ++j) {
            float vv = sv[i * 48 + j * 3 + c];
            a = fmaf(vv, sw[j * 16 + w], a);
            b = fmaf(vv, sw[(16 + j) * 16 + w], b);
            u = fmaf(vv, swu[j * 16 + w], u);
        }
        g_VA[(size_t)(n0 + i) * 48 + r] = a;
        g_VB[(size_t)(n0 + i) * 48 + r] = b;
        g_UVA[(size_t)(n0 + i) * 48 + r] = u;
    }
}

// ---------------------------------------------------------------------------
__global__ __launch_bounds__(256) void y_kernel(const float* __restrict__ s, int n) {
    __shared__ __align__(16) char ysm[6144 + 8704];
    const uint32_t smb = smem_to_u32(ysm);
    const int tid = threadIdx.x;
    const int lane = tid & 31;
    const int wid = tid >> 5;
    const int n0 = blockIdx.x * 128;

    const __half* Whi;
    const __half* Wlo;
    float* Y;
    if (blockIdx.y == 0)      { Whi = g_W1ahi; Wlo = g_W1alo; Y = g_Y1; }
    else if (blockIdx.y == 1) { Whi = g_W1bhi; Wlo = g_W1blo; Y = g_Y2; }
    else                      { Whi = g_U1ahi; Wlo = g_U1alo; Y = g_Z; }

    const int mw = (wid & 3) * 32;
    const int nw = (wid >> 2) * 64;
    const int arow = lane & 15;
    const int acol = lane >> 4;

    float acc[2][8][4];
#pragma unroll
    for (int mt = 0; mt < 2; ++mt)
#pragma unroll
        for (int nt = 0; nt < 8; ++nt)
#pragma unroll
            for (int r = 0; r < 4; ++r) acc[mt][nt][r] = 0.0f;

    for (int kt = 0; kt < 8; ++kt) {
        for (int q = tid; q < 2048; q += 256) {
            int e = q >> 4, kk = q & 15;
            int nd = min(n0 + e, n - 1);
            *(__half*)(ysm + e * 48 + kk * 2) =
                __float2half_rn(s[nd * 128 + kt * 16 + kk]);
        }
        for (int q = tid; q < 2048; q += 256) {
            int kk = q >> 7, nc = q & 127;
            *(__half*)(ysm + 6144 + kk * 272 + nc * 2) = Whi[(kt * 16 + kk) * 128 + nc];
            *(__half*)(ysm + 6144 + 4352 + kk * 272 + nc * 2) = Wlo[(kt * 16 + kk) * 128 + nc];
        }
        __syncthreads();
        uint32_t ah[2][4];
#pragma unroll
        for (int mt = 0; mt < 2; ++mt)
            ldsm4(smb + (mw + 16 * mt + arow) * 48 + acol * 16, ah[mt]);
#pragma unroll
        for (int nb = 0; nb < 4; ++nb) {
            uint32_t bh[4], bl[4];
            uint32_t baddr = smb + 6144 + arow * 272 + (nw + nb * 16 + acol * 8) * 2;
            ldsm4t(baddr, bh);
            ldsm4t(baddr + 4352, bl);
#pragma unroll
            for (int mt = 0; mt < 2; ++mt) {
                mma_f16(acc[mt][2 * nb],     ah[mt], bh);
                mma_f16(acc[mt][2 * nb + 1], ah[mt], bh + 2);
                mma_f16(acc[mt][2 * nb],     ah[mt], bl);
                mma_f16(acc[mt][2 * nb + 1], ah[mt], bl + 2);
            }
        }
        __syncthreads();
    }
#pragma unroll
    for (int mt = 0; mt < 2; ++mt) {
        int r0 = mw + 16 * mt + (lane >> 2);
#pragma unroll
        for (int nt = 0; nt < 8; ++nt) {
            int nc = nw + nt * 8 + (lane & 3) * 2;
            if (n0 + r0 < n) {
                float2 u = make_float2(acc[mt][nt][0], acc[mt][nt][1]);
                *(float2*)&Y[(size_t)(n0 + r0) * 128 + nc] = u;
            }
            if (n0 + r0 + 8 < n) {
                float2 u = make_float2(acc[mt][nt][2], acc[mt][nt][3]);
                *(float2*)&Y[(size_t)(n0 + r0 + 8) * 128 + nc] = u;
            }
        }
    }
}

// ===========================================================================
// Edge kernel: 64 edges/CTA, 256 threads, 3 CTAs/SM (reg-slim warp tile 16x64).
// smem (48704 B):
//   [0,17408)   T [64][136]fp16 (GEMM2 A). During GEMM1 overlay:
//               X dbl @0 (2x3072), snorm f32[64][36] @6144 (9216B)
//   [17408,34816) W dbl (2x8704)
//   [34816,38912) Wgp hi ; [38912,43008) Wgp lo   (staged after GEMM1)
//   [43008,47104) sg f32[64][16] (epi2)
//   [47104,48128) sev f32[64][4]
//   [48128,48192) wv32 f32[16]
//   [48192,48448) ssrc ; [48448,48704) sdst
// ===========================================================================
#define BE 64
#define OB_T     0
#define OB_X     0
#define OB_NORM  6144
#define OB_W     17408
#define OB_WGP   34816
#define OB_WGPLO 38912
#define OB_SG    43008
#define OB_SEV   47104
#define OB_WV32  48128
#define OB_SRC   48192
#define OB_DST   48448
#define EDGE_SMEM_BYTES 48704
#define XBUF(b)  (OB_X + (b) * 3072)
#define WBUF(b)  (OB_W + (b) * 8704)
#define WLO_OFF  4352

// edge-local X: k 0..31 edge_s, 32 edge_len, 33..65 vn (src16,dst16,|ev|), 66..79 zero
__device__ __forceinline__ float fetch_x80(int k, int e, int eg,
    const float* __restrict__ es, const float* snorm)
{
    if (k < 32)   return es[eg * 32 + k];
    if (k == 32)  return snorm[e * 36 + 32];
    if (k < 66)   return snorm[e * 36 + (k - 33)];
    return 0.0f;
}

__global__ __launch_bounds__(256, 3) void edge_kernel(
    const int* __restrict__ ei, const float* __restrict__ es,
    const float* __restrict__ ev,
    const float* __restrict__ b1, const float* __restrict__ b2,
    const float* __restrict__ Wv, int E)
{
    extern __shared__ __align__(16) char smraw[];
    float* smf = (float*)smraw;
    const uint32_t smb = smem_to_u32(smraw);

    const int tid = threadIdx.x;
    const int lane = tid & 31;
    const int wid = tid >> 5;
    const int e0 = blockIdx.x * BE;
    const int nval = min(BE, E - e0);

    int* ssrc = (int*)(smraw + OB_SRC);
    int* sdst = (int*)(smraw + OB_DST);
    float* snorm = (float*)(smraw + OB_NORM);

    // ---- phase 1: indices, vn staging, ev ----
    if (tid < BE) {
        int ee = e0 + min(tid, nval - 1);
        ssrc[tid] = ei[ee];
        sdst[tid] = ei[E + ee];
    }
    if (tid >= 240) {
        smf[OB_WV32 / 4 + (tid - 240)] = Wv[32 * 16 + (tid - 240)];
    }
    __syncthreads();
    for (int q = tid; q < 512; q += 256) {
        int e = q >> 3, p = q & 7;
        float4 t = (p < 4)
            ? *(const float4*)&g_vn[(size_t)ssrc[e] * 16 + p * 4]
            : *(const float4*)&g_vn[(size_t)sdst[e] * 16 + (p - 4) * 4];
        *(float4*)&snorm[e * 36 + (p < 4 ? p * 4 : 16 + (p - 4) * 4)] = t;
    }
    if (tid < BE) {
        int eg = e0 + min(tid, nval - 1);
        float a = ev[eg * 3], b = ev[eg * 3 + 1], c = ev[eg * 3 + 2];
        float nn = sqrtf(fmaxf(a * a + b * b + c * c, 1e-8f));
        snorm[tid * 36 + 32] = nn;
        float* se = smf + OB_SEV / 4 + tid * 4;
        se[0] = a; se[1] = b; se[2] = c; se[3] = nn;
    }
    __syncthreads();

    // warp tiling: 4 warps along M (16 edges each), 2 along N (64 cols)
    const int mw = (wid & 3) * 16;
    const int nw = (wid >> 2) * 64;
    const int arow = lane & 15;
    const int acol = lane >> 4;

    // X build: e = tid>>2, k-group (tid&3)*4 (4 k values = 2 packs)
    const int xe = tid >> 2;
    const int xkg = (tid & 3) * 4;
    // W staging coords (2 uint4/thread: hi and lo)
    const int wkk = tid >> 4;
    const int wn8 = (tid & 15) * 8;

    float acc[8][4];
    float gacc[2][4];

    // ---- acc init: Y1[src] + Y2[dst] fragments ----
    {
        const int r0 = mw + (lane >> 2);
        const int r1 = r0 + 8;
        const int cbase = nw + (lane & 3) * 2;
        const float* y1a = g_Y1 + (size_t)ssrc[r0] * 128;
        const float* y2a = g_Y2 + (size_t)sdst[r0] * 128;
        const float* y1b = g_Y1 + (size_t)ssrc[r1] * 128;
        const float* y2b = g_Y2 + (size_t)sdst[r1] * 128;
#pragma unroll
        for (int nt = 0; nt < 8; ++nt) {
            int nc = cbase + nt * 8;
            float2 a = *(const float2*)&y1a[nc];
            float2 b = *(const float2*)&y2a[nc];
            float2 c = *(const float2*)&y1b[nc];
            float2 d = *(const float2*)&y2b[nc];
            acc[nt][0] = a.x + b.x;
            acc[nt][1] = a.y + b.y;
            acc[nt][2] = c.x + d.x;
            acc[nt][3] = c.y + d.y;
        }
    }

    float xr[4];
    uint4 wh, wl;

    // ---- prologue: tile 0 ----
    {
        int eg = e0 + min(xe, nval - 1);
#pragma unroll
        for (int u = 0; u < 4; ++u)
            xr[u] = fetch_x80(xkg + u, xe, eg, es, snorm);
        wh = *(const uint4*)&g_W1phi[wkk * 128 + wn8];
        wl = *(const uint4*)&g_W1plo[wkk * 128 + wn8];
        *(uint32_t*)(smraw + XBUF(0) + xe * 48 + xkg * 2)       = pack_h2(xr[0], xr[1]);
        *(uint32_t*)(smraw + XBUF(0) + xe * 48 + (xkg + 2) * 2) = pack_h2(xr[2], xr[3]);
        *(uint4*)(smraw + WBUF(0) + wkk * 272 + wn8 * 2) = wh;
        *(uint4*)(smraw + WBUF(0) + WLO_OFF + wkk * 272 + wn8 * 2) = wl;
    }
    __syncthreads();

    // ================= GEMM1: edge-local part, K=80 (5 tiles) ================
    for (int kt = 0; kt < 5; ++kt) {
        const int cur = kt & 1, nxt = cur ^ 1;
        const bool more = (kt + 1 < 5);
        if (more) {
            int kbase = (kt + 1) * 16;
            int eg = e0 + min(xe, nval - 1);
#pragma unroll
            for (int u = 0; u < 4; ++u)
                xr[u] = fetch_x80(kbase + xkg + u, xe, eg, es, snorm);
            wh = *(const uint4*)&g_W1phi[(kbase + wkk) * 128 + wn8];
            wl = *(const uint4*)&g_W1plo[(kbase + wkk) * 128 + wn8];
        }
        {
            uint32_t ah[4];
            ldsm4(smb + XBUF(cur) + (mw + arow) * 48 + acol * 16, ah);
#pragma unroll
            for (int nb = 0; nb < 4; ++nb) {
                uint32_t bh[4], bl[4];
                uint32_t baddr = smb + WBUF(cur) + arow * 272 + (nw + nb * 16 + acol * 8) * 2;
                ldsm4t(baddr, bh);
                ldsm4t(baddr + WLO_OFF, bl);
                mma_f16(acc[2 * nb],     ah, bh);
                mma_f16(acc[2 * nb + 1], ah, bh + 2);
                mma_f16(acc[2 * nb],     ah, bl);
                mma_f16(acc[2 * nb + 1], ah, bl + 2);
            }
        }
        if (more) {
            *(uint32_t*)(smraw + XBUF(nxt) + xe * 48 + xkg * 2)       = pack_h2(xr[0], xr[1]);
            *(uint32_t*)(smraw + XBUF(nxt) + xe * 48 + (xkg + 2) * 2) = pack_h2(xr[2], xr[3]);
            *(uint4*)(smraw + WBUF(nxt) + wkk * 272 + wn8 * 2) = wh;
            *(uint4*)(smraw + WBUF(nxt) + WLO_OFF + wkk * 272 + wn8 * 2) = wl;
        }
        __syncthreads();
    }

    // ---- epilogue 1: +b1, silu -> T fp16 (X/snorm dead; T overlays them) ----
    {
        int r0 = mw + (lane >> 2);
#pragma unroll
        for (int nt = 0; nt < 8; ++nt) {
            int n = nw + nt * 8 + (lane & 3) * 2;
            float2 bb = *(const float2*)&b1[n];
            float h0 = acc[nt][0] + bb.x, h1 = acc[nt][1] + bb.y;
            float h2 = acc[nt][2] + bb.x, h3 = acc[nt][3] + bb.y;
            float t0 = h0 * sigmoidf_(h0), t1 = h1 * sigmoidf_(h1);
            float t2 = h2 * sigmoidf_(h2), t3 = h3 * sigmoidf_(h3);
            *(uint32_t*)(smraw + OB_T + r0 * 272 + n * 2)       = pack_h2(t0, t1);
            *(uint32_t*)(smraw + OB_T + (r0 + 8) * 272 + n * 2) = pack_h2(t2, t3);
        }
    }
    // stage Wgp hi/lo (own region, no conflict)
    for (int q = tid; q < 1024; q += 256) {
        ((uint32_t*)(smraw + OB_WGP))[q]   = ((const uint32_t*)g_Wgphi)[q];
        ((uint32_t*)(smraw + OB_WGPLO))[q] = ((const uint32_t*)g_Wgplo)[q];
    }
    __syncthreads();

    // ================= GEMM2: m_s = T @ W2 (K=128) + fused gate ==============
#pragma unroll
    for (int nt = 0; nt < 8; ++nt)
#pragma unroll
        for (int r = 0; r < 4; ++r) acc[nt][r] = 0.0f;
#pragma unroll
    for (int gn = 0; gn < 2; ++gn)
#pragma unroll
        for (int r = 0; r < 4; ++r) gacc[gn][r] = 0.0f;

    wh = *(const uint4*)&g_W2hi[wkk * 128 + wn8];
    wl = *(const uint4*)&g_W2lo[wkk * 128 + wn8];
    *(uint4*)(smraw + WBUF(0) + wkk * 272 + wn8 * 2) = wh;
    *(uint4*)(smraw + WBUF(0) + WLO_OFF + wkk * 272 + wn8 * 2) = wl;
    __syncthreads();

    for (int kt = 0; kt < 8; ++kt) {
        const int cur = kt & 1, nxt = cur ^ 1;
        const bool more = (kt + 1 < 8);
        if (more) {
            wh = *(const uint4*)&g_W2hi[((kt + 1) * 16 + wkk) * 128 + wn8];
            wl = *(const uint4*)&g_W2lo[((kt + 1) * 16 + wkk) * 128 + wn8];
        }
        {
            uint32_t ah[4];
            ldsm4(smb + OB_T + (mw + arow) * 272 + (kt * 16 + acol * 8) * 2, ah);
#pragma unroll
            for (int nb = 0; nb < 4; ++nb) {
                uint32_t bh[4], bl[4];
                uint32_t baddr = smb + WBUF(cur) + arow * 272 + (nw + nb * 16 + acol * 8) * 2;
                ldsm4t(baddr, bh);
                ldsm4t(baddr + WLO_OFF, bl);
                mma_f16(acc[2 * nb],     ah, bh);
                mma_f16(acc[2 * nb + 1], ah, bh + 2);
                mma_f16(acc[2 * nb],     ah, bl);
                mma_f16(acc[2 * nb + 1], ah, bl + 2);
            }
            // fused gate: only N-half-0 warps (they cover all 64 rows)
            if (wid < 4) {
                uint32_t gh[4], gl[4];
                uint32_t gaddr = smb + OB_WGP + kt * 512 + arow * 32 + acol * 16;
                ldsm4t(gaddr, gh);
                ldsm4t(gaddr + (OB_WGPLO - OB_WGP), gl);
                mma_f16(gacc[0], ah, gh);
                mma_f16(gacc[1], ah, gh + 2);
                mma_f16(gacc[0], ah, gl);
                mma_f16(gacc[1], ah, gl + 2);
            }
        }
        if (more) {
            *(uint4*)(smraw + WBUF(nxt) + wkk * 272 + wn8 * 2) = wh;
            *(uint4*)(smraw + WBUF(nxt) + WLO_OFF + wkk * 272 + wn8 * 2) = wl;
        }
        __syncthreads();
    }

    // ---- epilogue 2: direct red.v2 scatter of m_s (+b2); gates -> sg ----
    float* sg = smf + OB_SG / 4;  // [64][16]
    {
        int r0 = mw + (lane >> 2);
        int r1 = r0 + 8;
        float* d0 = &g_agg_s[(size_t)sdst[r0] * 128];
        float* d1 = &g_agg_s[(size_t)sdst[r1] * 128];
        bool v0 = (r0 < nval), v1 = (r1 < nval);
#pragma unroll
        for (int nt = 0; nt < 8; ++nt) {
            int n = nw + nt * 8 + (lane & 3) * 2;
            float2 bb = *(const float2*)&b2[n];
            if (v0) red2(d0 + n, acc[nt][0] + bb.x, acc[nt][1] + bb.y);
            if (v1) red2(d1 + n, acc[nt][2] + bb.x, acc[nt][3] + bb.y);
        }
        if (wid < 4) {
#pragma unroll
            for (int gn = 0; gn < 2; ++gn) {
                int col = gn * 8 + (lane & 3) * 2;
                float b0 = g_bgp[col], b1g = g_bgp[col + 1];
                sg[r0 * 16 + col]     = sigmoidf_(gacc[gn][0] + b0);
                sg[r0 * 16 + col + 1] = sigmoidf_(gacc[gn][1] + b1g);
                sg[r1 * 16 + col]     = sigmoidf_(gacc[gn][2] + b0);
                sg[r1 * 16 + col + 1] = sigmoidf_(gacc[gn][3] + b1g);
            }
        }
    }
    __syncthreads();

    // ---- v projection via precomputed VA/VB, scatter-add ----
    for (int q = tid; q < BE * 12; q += 256) {
        int e = q / 12, rq = q - e * 12;
        if (e >= nval) continue;
        float4 a4 = *(const float4*)&g_VA[(size_t)ssrc[e] * 48 + rq * 4];
        float4 b4 = *(const float4*)&g_VB[(size_t)sdst[e] * 48 + rq * 4];
        float av[4] = {a4.x + b4.x, a4.y + b4.y, a4.z + b4.z, a4.w + b4.w};
        float out[4];
#pragma unroll
        for (int u = 0; u < 4; ++u) {
            int r = rq * 4 + u, w = r / 3, c3 = r - w * 3;
            float val = av[u] + smf[OB_SEV / 4 + e * 4 + c3] * smf[OB_WV32 / 4 + w];
            out[u] = val * sg[e * 16 + w];
        }
        red4(&g_agg_v[(size_t)sdst[e] * 48 + rq * 4], out[0], out[1], out[2], out[3]);
    }
}

// ---------------------------------------------------------------------------
// Node update kernel (r12)
// ---------------------------------------------------------------------------
__global__ __launch_bounds__(128) void node_kernel(
    const float* __restrict__ s, const float* __restrict__ v,
    const float* __restrict__ W1, const float* __restrict__ b1,
    const float* __restrict__ W2, const float* __restrict__ b2,
    const float* __restrict__ Wv, const float* __restrict__ Wg,
    const float* __restrict__ bg, const float* __restrict__ lng,
    const float* __restrict__ lnb,
    float* __restrict__ out_s, float* __restrict__ out_v, int n)
{
    __shared__ float xu[8][164];
    __shared__ float vinB[8][48];
    __shared__ float tt[8][128];
    __shared__ float dsm[8][132];
    __shared__ float gate[8][16];
    __shared__ float rsum[8][4], rsq[8][4];

    const int tid = threadIdx.x;
    const int n0 = blockIdx.x * 8;

    for (int idx = tid; idx < 8 * 144; idx += 128) {
        int i = idx / 144, k = idx - i * 144;
        int nd = min(n0 + i, n - 1);
        xu[i][k] = (k < 128) ? g_agg_s[(size_t)nd * 128 + k]
                             : g_vn[(size_t)nd * 16 + (k - 128)];
    }
    for (int idx = tid; idx < 8 * 48; idx += 128) {
        int i = idx / 48, k = idx - i * 48;
        int nd = min(n0 + i, n - 1);
        vinB[i][k] = g_agg_v[(size_t)nd * 48 + k];
    }
    __syncthreads();
    for (int idx = tid; idx < 8 * 16; idx += 128) {
        int i = idx >> 4, j = idx & 15;
        float a = vinB[i][j * 3], b = vinB[i][j * 3 + 1], c = vinB[i][j * 3 + 2];
        xu[i][144 + j] = sqrtf(fmaxf(a * a + b * b + c * c, 1e-8f));
    }
    __syncthreads();

    const int c = tid;
    float acc[8];
    {
        float bb = b1[c];
#pragma unroll
        for (int i = 0; i < 8; ++i) {
            int nd = min(n0 + i, n - 1);
            acc[i] = g_Z[(size_t)nd * 128 + c] + bb;
        }
    }
    for (int k = 0; k < 160; ++k) {
        float w = W1[(128 + k) * 128 + c];
#pragma unroll
        for (int i = 0; i < 8; ++i) acc[i] = fmaf(xu[i][k], w, acc[i]);
    }
#pragma unroll
    for (int i = 0; i < 8; ++i) {
        float h = acc[i];
        tt[i][c] = h * sigmoidf_(h);
    }
    __syncthreads();

    float acc2[8];
    {
        float bb = b2[c];
#pragma unroll
        for (int i = 0; i < 8; ++i) acc2[i] = bb;
    }
    for (int k = 0; k < 128; ++k) {
        float w = W2[k * 128 + c];
#pragma unroll
        for (int i = 0; i < 8; ++i) acc2[i] = fmaf(tt[i][k], w, acc2[i]);
    }
#pragma unroll
    for (int i = 0; i < 8; ++i) dsm[i][c] = acc2[i];
    __syncthreads();

    {
        int i = tid >> 4, w = tid & 15;
        float g = bg[w];
        for (int cc = 0; cc < 128; ++cc)
            g = fmaf(dsm[i][cc], Wg[cc * 16 + w], g);
        gate[i][w] = sigmoidf_(g);
    }

    float val[8];
#pragma unroll
    for (int i = 0; i < 8; ++i) {
        int nd = min(n0 + i, n - 1);
        val[i] = s[nd * 128 + c] + acc2[i];
    }
    const int lane = tid & 31, wq = tid >> 5;
    float psum[8], psq[8];
#pragma unroll
    for (int i = 0; i < 8; ++i) { psum[i] = val[i]; psq[i] = val[i] * val[i]; }
#pragma unroll
    for (int off = 16; off > 0; off >>= 1) {
#pragma unroll
        for (int i = 0; i < 8; ++i) {
            psum[i] += __shfl_xor_sync(0xffffffffu, psum[i], off);
            psq[i]  += __shfl_xor_sync(0xffffffffu, psq[i],  off);
        }
    }
    if (lane == 0) {
#pragma unroll
        for (int i = 0; i < 8; ++i) { rsum[i][wq] = psum[i]; rsq[i][wq] = psq[i]; }
    }
    __syncthreads();

#pragma unroll
    for (int i = 0; i < 8; ++i) {
        if (n0 + i >= n) continue;
        float sum = rsum[i][0] + rsum[i][1] + rsum[i][2] + rsum[i][3];
        float sq  = rsq[i][0] + rsq[i][1] + rsq[i][2] + rsq[i][3];
        float mu  = sum * (1.0f / 128.0f);
        float var = sq * (1.0f / 128.0f) - mu * mu;
        float o = (val[i] - mu) * rsqrtf(var + 1e-5f) * lng[c] + lnb[c];
        out_s[(n0 + i) * 128 + c] = o;
    }

    for (int q = tid; q < 8 * 48; q += 128) {
        int i = q / 48, r = q - i * 48;
        if (n0 + i >= n) continue;
        int w = r / 3, cc = r - w * 3;
        float a = g_UVA[(size_t)(n0 + i) * 48 + r];
#pragma unroll
        for (int j = 0; j < 16; ++j)
            a = fmaf(vinB[i][j * 3 + cc], Wv[(16 + j) * 16 + w], a);
        a *= gate[i][w];
        out_v[(n0 + i) * 48 + r] = v[(n0 + i) * 48 + r] + a;
    }
}

// ---------------------------------------------------------------------------
extern "C" void kernel_launch(void* const* d_in, const int* in_sizes, int n_in,
                              void* d_out, int out_size)
{
    const float* s   = (const float*)d_in[0];
    const float* v   = (const float*)d_in[1];
    const int*   ei  = (const int*)  d_in[2];
    const float* es  = (const float*)d_in[3];
    const float* ev  = (const float*)d_in[4];
    const float* mW1 = (const float*)d_in[5];
    const float* mb1 = (const float*)d_in[6];
    const float* mW2 = (const float*)d_in[7];
    const float* mb2 = (const float*)d_in[8];
    const float* mWv = (const float*)d_in[9];
    const float* mWg = (const float*)d_in[10];
    const float* mbg = (const float*)d_in[11];
    const float* uW1 = (const float*)d_in[12];
    const float* ub1 = (const float*)d_in[13];
    const float* uW2 = (const float*)d_in[14];
    const float* ub2 = (const float*)d_in[15];
    const float* uWv = (const float*)d_in[16];
    const float* uWg = (const float*)d_in[17];
    const float* ubg = (const float*)d_in[18];
    const float* lng = (const float*)d_in[19];
    const float* lnb = (const float*)d_in[20];

    const int n = in_sizes[0] / 128;
    const int E = in_sizes[2] / 2;

    float* out_s = (float*)d_out;
    float* out_v = out_s + (size_t)n * 128;

    cudaFuncSetAttribute(edge_kernel,
                         cudaFuncAttributeMaxDynamicSharedMemorySize,
                         EDGE_SMEM_BYTES);

    zero_kernel<<<(n * 176 + 255) / 256, 256>>>(n);
    prep_weights<<<(77840 + 255) / 256, 256>>>(mW1, mW2, mb2, mWg, mbg, uW1);
    prep_nodes<<<(n + 31) / 32, 256>>>(v, mWv, uWv, n);
    y_kernel<<<dim3((n + 127) / 128, 3), 256>>>(s, n);

    edge_kernel<<<(E + BE - 1) / BE, 256, EDGE_SMEM_BYTES>>>(
        ei, es, ev, mb1, mb2, mWv, E);

    node_kernel<<<(n + 7) / 8, 128>>>(
        s, v, uW1, ub1, uW2, ub2, uWv, uWg, ubg, lng, lnb,
        out_s, out_v, n);
}

// round 15
// speedup vs baseline: 1.3154x; 1.1287x over previous
#include <cuda_runtime.h>
#include <cuda_fp16.h>
#include <math.h>
#include <stdint.h>

// Problem constants: N=20000, E=640000, S=128, V=16, E_DIM=32
#define MAXN 20000

__device__ float g_agg_s[MAXN * 128];
__device__ float g_agg_v[MAXN * 48];

__device__ float g_Y1[MAXN * 128];
__device__ float g_Y2[MAXN * 128];
__device__ float g_Z[MAXN * 128];
__device__ float g_vn[MAXN * 16];
__device__ float g_VA[MAXN * 48];
__device__ float g_VB[MAXN * 48];
__device__ float g_UVA[MAXN * 48];

__device__ __half g_W1ahi[128 * 128];
__device__ __half g_W1alo[128 * 128];
__device__ __half g_W1bhi[128 * 128];
__device__ __half g_W1blo[128 * 128];
__device__ __half g_W1phi[80 * 128];
__device__ __half g_W1plo[80 * 128];
__device__ __half g_W2hi[128 * 128];
__device__ __half g_W2lo[128 * 128];
__device__ __half g_Wgphi[128 * 16];
__device__ __half g_Wgplo[128 * 16];
__device__ float  g_bgp[16];
__device__ __half g_U1ahi[128 * 128];
__device__ __half g_U1alo[128 * 128];

__device__ __forceinline__ float sigmoidf_(float x) {
    return 1.0f / (1.0f + __expf(-x));
}
__device__ __forceinline__ uint32_t smem_to_u32(const void* p) {
    uint32_t a;
    asm("{ .reg .u64 t; cvta.to.shared.u64 t, %1; cvt.u32.u64 %0, t; }"
        : "=r"(a) : "l"(p));
    return a;
}
__device__ __forceinline__ void ldsm4(uint32_t addr, uint32_t* r) {
    asm volatile("ldmatrix.sync.aligned.m8n8.x4.shared.b16 {%0,%1,%2,%3}, [%4];"
        : "=r"(r[0]), "=r"(r[1]), "=r"(r[2]), "=r"(r[3]) : "r"(addr));
}
__device__ __forceinline__ void ldsm4t(uint32_t addr, uint32_t* r) {
    asm volatile("ldmatrix.sync.aligned.m8n8.x4.trans.shared.b16 {%0,%1,%2,%3}, [%4];"
        : "=r"(r[0]), "=r"(r[1]), "=r"(r[2]), "=r"(r[3]) : "r"(addr));
}
__device__ __forceinline__ void mma_f16(float* c, const uint32_t* a, const uint32_t* b) {
    asm volatile(
        "mma.sync.aligned.m16n8k16.row.col.f32.f16.f16.f32 "
        "{%0,%1,%2,%3}, {%4,%5,%6,%7}, {%8,%9}, {%0,%1,%2,%3};"
        : "+f"(c[0]), "+f"(c[1]), "+f"(c[2]), "+f"(c[3])
        : "r"(a[0]), "r"(a[1]), "r"(a[2]), "r"(a[3]), "r"(b[0]), "r"(b[1]));
}
__device__ __forceinline__ uint32_t pack_h2(float x0, float x1) {
    __half2 t = __floats2half2_rn(x0, x1);
    return *(uint32_t*)&t;
}
__device__ __forceinline__ void red4(float* p, float a, float b, float c, float d) {
    asm volatile("red.global.add.v4.f32 [%0], {%1, %2, %3, %4};"
        :: "l"(p), "f"(a), "f"(b), "f"(c), "f"(d) : "memory");
}
__device__ __forceinline__ void red2(float* p, float a, float b) {
    asm volatile("red.global.add.v2.f32 [%0], {%1, %2};"
        :: "l"(p), "f"(a), "f"(b) : "memory");
}
__device__ __forceinline__ void cp_async16(uint32_t saddr, const void* gptr) {
    asm volatile(
        "{ .reg .u64 g; cvta.to.global.u64 g, %1; "
        "cp.async.cg.shared.global [%0], [g], 16; }"
        :: "r"(saddr), "l"(gptr) : "memory");
}
#define CP_COMMIT() asm volatile("cp.async.commit_group;" ::: "memory")
#define CP_WAIT0()  asm volatile("cp.async.wait_group 0;" ::: "memory")

// ---------------------------------------------------------------------------
__global__ void zero_kernel(int n) {
    int total = n * 176;
    for (int i = blockIdx.x * blockDim.x + threadIdx.x; i < total;
         i += gridDim.x * blockDim.x) {
        if (i < n * 128) g_agg_s[i] = 0.0f;
        else             g_agg_v[i - n * 128] = 0.0f;
    }
}

__global__ void prep_weights(const float* __restrict__ W1,
                             const float* __restrict__ W2,
                             const float* __restrict__ b2,
                             const float* __restrict__ Wg,
                             const float* __restrict__ bg,
                             const float* __restrict__ uW1) {
    int i = blockIdx.x * blockDim.x + threadIdx.x;
    if (i < 80 * 128) {
        int k = i >> 7;
        float val = (k < 66) ? W1[(256 + k) * 128 + (i & 127)] : 0.0f;
        __half h = __float2half_rn(val);
        g_W1phi[i] = h;
        g_W1plo[i] = __float2half_rn(val - __half2float(h));
    } else if (i < 26624) {
        int j = i - 10240;
        float val = W1[j];
        __half h = __float2half_rn(val);
        g_W1ahi[j] = h;
        g_W1alo[j] = __float2half_rn(val - __half2float(h));
    } else if (i < 43008) {
        int j = i - 26624;
        float val = W1[128 * 128 + j];
        __half h = __float2half_rn(val);
        g_W1bhi[j] = h;
        g_W1blo[j] = __float2half_rn(val - __half2float(h));
    } else if (i < 59392) {
        int j = i - 43008;
        float val = W2[j];
        __half h = __float2half_rn(val);
        g_W2hi[j] = h;
        g_W2lo[j] = __float2half_rn(val - __half2float(h));
    } else if (i < 61440) {
        int j = i - 59392;
        int k = j >> 4, w = j & 15;
        float a = 0.0f;
        for (int c = 0; c < 128; ++c)
            a = fmaf(W2[k * 128 + c], Wg[c * 16 + w], a);
        __half h = __float2half_rn(a);
        g_Wgphi[j] = h;
        g_Wgplo[j] = __float2half_rn(a - __half2float(h));
    } else if (i < 61456) {
        int w = i - 61440;
        float a = bg[w];
        for (int c = 0; c < 128; ++c)
            a = fmaf(b2[c], Wg[c * 16 + w], a);
        g_bgp[w] = a;
    } else if (i < 77840) {
        int j = i - 61456;
        float val = uW1[j];
        __half h = __float2half_rn(val);
        g_U1ahi[j] = h;
        g_U1alo[j] = __float2half_rn(val - __half2float(h));
    }
}

// ---------------------------------------------------------------------------
__global__ __launch_bounds__(256) void prep_nodes(const float* __restrict__ v,
                                                  const float* __restrict__ Wv,
                                                  const float* __restrict__ uWv,
                                                  int n) {
    __shared__ float sv[32 * 48];
    __shared__ float sw[528];
    __shared__ float swu[256];
    const int tid = threadIdx.x;
    const int n0 = blockIdx.x * 32;

    for (int q = tid; q < 32 * 48; q += 256) {
        int i = q / 48, k = q - i * 48;
        int nd = min(n0 + i, n - 1);
        sv[q] = v[(size_t)nd * 48 + k];
    }
    for (int q = tid; q < 528; q += 256) sw[q] = Wv[q];
    for (int q = tid; q < 256; q += 256) swu[q] = uWv[q];
    __syncthreads();

    for (int q = tid; q < 32 * 16; q += 256) {
        int i = q >> 4, j = q & 15;
        if (n0 + i >= n) continue;
        float a = sv[i * 48 + j * 3], b = sv[i * 48 + j * 3 + 1],
              c = sv[i * 48 + j * 3 + 2];
        g_vn[(size_t)(n0 + i) * 16 + j] = sqrtf(fmaxf(a * a + b * b + c * c, 1e-8f));
    }
    for (int q = tid; q < 32 * 48; q += 256) {
        int i = q / 48, r = q - i * 48;
        if (n0 + i >= n) continue;
        int w = r / 3, c = r - w * 3;
        float a = 0.0f, b = 0.0f, u = 0.0f;
#pragma unroll
        for (int j = 0; j < 16; ++j) {
            float vv = sv[i * 48 + j * 3 + c];
            a = fmaf(vv, sw[j * 16 + w], a);
            b = fmaf(vv, sw[(16 + j) * 16 + w], b);
            u = fmaf(vv, swu[j * 16 + w], u);
        }
        g_VA[(size_t)(n0 + i) * 48 + r] = a;
        g_VB[(size_t)(n0 + i) * 48 + r] = b;
        g_UVA[(size_t)(n0 + i) * 48 + r] = u;
    }
}

// ---------------------------------------------------------------------------
// Y kernel: 64-row M tiles for occupancy. blockIdx.y selects output.
// ---------------------------------------------------------------------------
__global__ __launch_bounds__(256) void y_kernel(const float* __restrict__ s, int n) {
    __shared__ __align__(16) char ysm[3072 + 8704];
    const uint32_t smb = smem_to_u32(ysm);
    const int tid = threadIdx.x;
    const int lane = tid & 31;
    const int wid = tid >> 5;
    const int n0 = blockIdx.x * 64;

    const __half* Whi;
    const __half* Wlo;
    float* Y;
    if (blockIdx.y == 0)      { Whi = g_W1ahi; Wlo = g_W1alo; Y = g_Y1; }
    else if (blockIdx.y == 1) { Whi = g_W1bhi; Wlo = g_W1blo; Y = g_Y2; }
    else                      { Whi = g_U1ahi; Wlo = g_U1alo; Y = g_Z; }

    const int mw = (wid & 3) * 16;
    const int nw = (wid >> 2) * 64;
    const int arow = lane & 15;
    const int acol = lane >> 4;
    const int xe = tid >> 2;
    const int xkg = (tid & 3) * 4;

    float acc[8][4];
#pragma unroll
    for (int nt = 0; nt < 8; ++nt)
#pragma unroll
        for (int r = 0; r < 4; ++r) acc[nt][r] = 0.0f;

    for (int kt = 0; kt < 8; ++kt) {
        {
            int nd = min(n0 + xe, n - 1);
            const float* sp = s + (size_t)nd * 128 + kt * 16 + xkg;
            *(uint32_t*)(ysm + xe * 48 + xkg * 2)       = pack_h2(sp[0], sp[1]);
            *(uint32_t*)(ysm + xe * 48 + (xkg + 2) * 2) = pack_h2(sp[2], sp[3]);
        }
        for (int q = tid; q < 2048; q += 256) {
            int kk = q >> 7, nc = q & 127;
            *(__half*)(ysm + 3072 + kk * 272 + nc * 2) = Whi[(kt * 16 + kk) * 128 + nc];
            *(__half*)(ysm + 3072 + 4352 + kk * 272 + nc * 2) = Wlo[(kt * 16 + kk) * 128 + nc];
        }
        __syncthreads();
        uint32_t ah[4];
        ldsm4(smb + (mw + arow) * 48 + acol * 16, ah);
#pragma unroll
        for (int nb = 0; nb < 4; ++nb) {
            uint32_t bh[4], bl[4];
            uint32_t baddr = smb + 3072 + arow * 272 + (nw + nb * 16 + acol * 8) * 2;
            ldsm4t(baddr, bh);
            ldsm4t(baddr + 4352, bl);
            mma_f16(acc[2 * nb],     ah, bh);
            mma_f16(acc[2 * nb + 1], ah, bh + 2);
            mma_f16(acc[2 * nb],     ah, bl);
            mma_f16(acc[2 * nb + 1], ah, bl + 2);
        }
        __syncthreads();
    }
    {
        int r0 = mw + (lane >> 2);
#pragma unroll
        for (int nt = 0; nt < 8; ++nt) {
            int nc = nw + nt * 8 + (lane & 3) * 2;
            if (n0 + r0 < n) {
                float2 u = make_float2(acc[nt][0], acc[nt][1]);
                *(float2*)&Y[(size_t)(n0 + r0) * 128 + nc] = u;
            }
            if (n0 + r0 + 8 < n) {
                float2 u = make_float2(acc[nt][2], acc[nt][3]);
                *(float2*)&Y[(size_t)(n0 + r0 + 8) * 128 + nc] = u;
            }
        }
    }
}

// ===========================================================================
// Edge kernel: 64 edges/CTA, 256 threads, target 4 CTAs/SM.
// cp.async W pipeline; GEMM1 single-term W (hi only); GEMM2 2-term.
// smem layout identical to r13 (48704 B).
// ===========================================================================
#define BE 64
#define OB_T     0
#define OB_X     0
#define OB_NORM  6144
#define OB_W     17408
#define OB_WGP   34816
#define OB_WGPLO 38912
#define OB_SG    43008
#define OB_SEV   47104
#define OB_WV32  48128
#define OB_SRC   48192
#define OB_DST   48448
#define EDGE_SMEM_BYTES 48704
#define XBUF(b)  (OB_X + (b) * 3072)
#define WBUF(b)  (OB_W + (b) * 8704)
#define WLO_OFF  4352

__device__ __forceinline__ float fetch_x80(int k, int e, int eg,
    const float* __restrict__ es, const float* snorm)
{
    if (k < 32)   return es[eg * 32 + k];
    if (k == 32)  return snorm[e * 36 + 32];
    if (k < 66)   return snorm[e * 36 + (k - 33)];
    return 0.0f;
}

__global__ __launch_bounds__(256, 4) void edge_kernel(
    const int* __restrict__ ei, const float* __restrict__ es,
    const float* __restrict__ ev,
    const float* __restrict__ b1, const float* __restrict__ b2,
    const float* __restrict__ Wv, int E)
{
    extern __shared__ __align__(16) char smraw[];
    float* smf = (float*)smraw;
    const uint32_t smb = smem_to_u32(smraw);

    const int tid = threadIdx.x;
    const int lane = tid & 31;
    const int wid = tid >> 5;
    const int e0 = blockIdx.x * BE;
    const int nval = min(BE, E - e0);

    int* ssrc = (int*)(smraw + OB_SRC);
    int* sdst = (int*)(smraw + OB_DST);
    float* snorm = (float*)(smraw + OB_NORM);

    // ---- phase 1 ----
    if (tid < BE) {
        int ee = e0 + min(tid, nval - 1);
        ssrc[tid] = ei[ee];
        sdst[tid] = ei[E + ee];
    }
    if (tid >= 240) {
        smf[OB_WV32 / 4 + (tid - 240)] = Wv[32 * 16 + (tid - 240)];
    }
    __syncthreads();
    for (int q = tid; q < 512; q += 256) {
        int e = q >> 3, p = q & 7;
        float4 t = (p < 4)
            ? *(const float4*)&g_vn[(size_t)ssrc[e] * 16 + p * 4]
            : *(const float4*)&g_vn[(size_t)sdst[e] * 16 + (p - 4) * 4];
        *(float4*)&snorm[e * 36 + (p < 4 ? p * 4 : 16 + (p - 4) * 4)] = t;
    }
    if (tid < BE) {
        int eg = e0 + min(tid, nval - 1);
        float a = ev[eg * 3], b = ev[eg * 3 + 1], c = ev[eg * 3 + 2];
        float nn = sqrtf(fmaxf(a * a + b * b + c * c, 1e-8f));
        snorm[tid * 36 + 32] = nn;
        float* se = smf + OB_SEV / 4 + tid * 4;
        se[0] = a; se[1] = b; se[2] = c; se[3] = nn;
    }
    __syncthreads();

    const int mw = (wid & 3) * 16;
    const int nw = (wid >> 2) * 64;
    const int arow = lane & 15;
    const int acol = lane >> 4;
    const int xe = tid >> 2;
    const int xkg = (tid & 3) * 4;
    const int wkk = tid >> 4;
    const int wn8 = (tid & 15) * 8;
    const uint32_t wdst_rel = (uint32_t)(wkk * 272 + wn8 * 2);

    float acc[8][4];
    float gacc[2][4];

    // ---- acc init: Y1[src] + Y2[dst] fragments ----
    {
        const int r0 = mw + (lane >> 2);
        const int r1 = r0 + 8;
        const int cbase = nw + (lane & 3) * 2;
        const float* y1a = g_Y1 + (size_t)ssrc[r0] * 128;
        const float* y2a = g_Y2 + (size_t)sdst[r0] * 128;
        const float* y1b = g_Y1 + (size_t)ssrc[r1] * 128;
        const float* y2b = g_Y2 + (size_t)sdst[r1] * 128;
#pragma unroll
        for (int nt = 0; nt < 8; ++nt) {
            int nc = cbase + nt * 8;
            float2 a = *(const float2*)&y1a[nc];
            float2 b = *(const float2*)&y2a[nc];
            float2 c = *(const float2*)&y1b[nc];
            float2 d = *(const float2*)&y2b[nc];
            acc[nt][0] = a.x + b.x;
            acc[nt][1] = a.y + b.y;
            acc[nt][2] = c.x + d.x;
            acc[nt][3] = c.y + d.y;
        }
    }

    float xr[4];

    // ---- prologue: tile 0 (W via cp.async, X via regs) ----
    {
        cp_async16(smb + WBUF(0) + wdst_rel, &g_W1phi[wkk * 128 + wn8]);
        CP_COMMIT();
        int eg = e0 + min(xe, nval - 1);
#pragma unroll
        for (int u = 0; u < 4; ++u)
            xr[u] = fetch_x80(xkg + u, xe, eg, es, snorm);
        *(uint32_t*)(smraw + XBUF(0) + xe * 48 + xkg * 2)       = pack_h2(xr[0], xr[1]);
        *(uint32_t*)(smraw + XBUF(0) + xe * 48 + (xkg + 2) * 2) = pack_h2(xr[2], xr[3]);
        CP_WAIT0();
    }
    __syncthreads();

    // ================= GEMM1: edge-local, K=80 (5 tiles), W hi only ==========
    for (int kt = 0; kt < 5; ++kt) {
        const int cur = kt & 1, nxt = cur ^ 1;
        const bool more = (kt + 1 < 5);
        if (more) {
            int kbase = (kt + 1) * 16;
            cp_async16(smb + WBUF(nxt) + wdst_rel, &g_W1phi[(kbase + wkk) * 128 + wn8]);
            CP_COMMIT();
            int eg = e0 + min(xe, nval - 1);
#pragma unroll
            for (int u = 0; u < 4; ++u)
                xr[u] = fetch_x80(kbase + xkg + u, xe, eg, es, snorm);
        }
        {
            uint32_t ah[4];
            ldsm4(smb + XBUF(cur) + (mw + arow) * 48 + acol * 16, ah);
#pragma unroll
            for (int nb = 0; nb < 4; ++nb) {
                uint32_t bh[4];
                uint32_t baddr = smb + WBUF(cur) + arow * 272 + (nw + nb * 16 + acol * 8) * 2;
                ldsm4t(baddr, bh);
                mma_f16(acc[2 * nb],     ah, bh);
                mma_f16(acc[2 * nb + 1], ah, bh + 2);
            }
        }
        if (more) {
            *(uint32_t*)(smraw + XBUF(nxt) + xe * 48 + xkg * 2)       = pack_h2(xr[0], xr[1]);
            *(uint32_t*)(smraw + XBUF(nxt) + xe * 48 + (xkg + 2) * 2) = pack_h2(xr[2], xr[3]);
        }
        CP_WAIT0();
        __syncthreads();
    }

    // ---- between phases: issue W2 tile0 async, epilogue 1, Wgp staging ----
    cp_async16(smb + WBUF(0) + wdst_rel, &g_W2hi[wkk * 128 + wn8]);
    cp_async16(smb + WBUF(0) + WLO_OFF + wdst_rel, &g_W2lo[wkk * 128 + wn8]);
    CP_COMMIT();
    {
        int r0 = mw + (lane >> 2);
#pragma unroll
        for (int nt = 0; nt < 8; ++nt) {
            int n = nw + nt * 8 + (lane & 3) * 2;
            float2 bb = *(const float2*)&b1[n];
            float h0 = acc[nt][0] + bb.x, h1 = acc[nt][1] + bb.y;
            float h2 = acc[nt][2] + bb.x, h3 = acc[nt][3] + bb.y;
            float t0 = h0 * sigmoidf_(h0), t1 = h1 * sigmoidf_(h1);
            float t2 = h2 * sigmoidf_(h2), t3 = h3 * sigmoidf_(h3);
            *(uint32_t*)(smraw + OB_T + r0 * 272 + n * 2)       = pack_h2(t0, t1);
            *(uint32_t*)(smraw + OB_T + (r0 + 8) * 272 + n * 2) = pack_h2(t2, t3);
        }
    }
    for (int q = tid; q < 1024; q += 256) {
        ((uint32_t*)(smraw + OB_WGP))[q]   = ((const uint32_t*)g_Wgphi)[q];
        ((uint32_t*)(smraw + OB_WGPLO))[q] = ((const uint32_t*)g_Wgplo)[q];
    }
    CP_WAIT0();
    __syncthreads();

    // ================= GEMM2: m_s = T @ W2 (K=128, 2-term) + fused gate ======
#pragma unroll
    for (int nt = 0; nt < 8; ++nt)
#pragma unroll
        for (int r = 0; r < 4; ++r) acc[nt][r] = 0.0f;
#pragma unroll
    for (int gn = 0; gn < 2; ++gn)
#pragma unroll
        for (int r = 0; r < 4; ++r) gacc[gn][r] = 0.0f;

    for (int kt = 0; kt < 8; ++kt) {
        const int cur = kt & 1, nxt = cur ^ 1;
        const bool more = (kt + 1 < 8);
        if (more) {
            int kbase = (kt + 1) * 16;
            cp_async16(smb + WBUF(nxt) + wdst_rel, &g_W2hi[(kbase + wkk) * 128 + wn8]);
            cp_async16(smb + WBUF(nxt) + WLO_OFF + wdst_rel, &g_W2lo[(kbase + wkk) * 128 + wn8]);
            CP_COMMIT();
        }
        {
            uint32_t ah[4];
            ldsm4(smb + OB_T + (mw + arow) * 272 + (kt * 16 + acol * 8) * 2, ah);
#pragma unroll
            for (int nb = 0; nb < 4; ++nb) {
                uint32_t bh[4], bl[4];
                uint32_t baddr = smb + WBUF(cur) + arow * 272 + (nw + nb * 16 + acol * 8) * 2;
                ldsm4t(baddr, bh);
                ldsm4t(baddr + WLO_OFF, bl);
                mma_f16(acc[2 * nb],     ah, bh);
                mma_f16(acc[2 * nb + 1], ah, bh + 2);
                mma_f16(acc[2 * nb],     ah, bl);
                mma_f16(acc[2 * nb + 1], ah, bl + 2);
            }
            if (wid < 4) {
                uint32_t gh[4], gl[4];
                uint32_t gaddr = smb + OB_WGP + kt * 512 + arow * 32 + acol * 16;
                ldsm4t(gaddr, gh);
                ldsm4t(gaddr + (OB_WGPLO - OB_WGP), gl);
                mma_f16(gacc[0], ah, gh);
                mma_f16(gacc[1], ah, gh + 2);
                mma_f16(gacc[0], ah, gl);
                mma_f16(gacc[1], ah, gl + 2);
            }
        }
        CP_WAIT0();
        __syncthreads();
    }

    // ---- epilogue 2: direct red.v2 scatter of m_s (+b2); gates -> sg ----
    float* sg = smf + OB_SG / 4;
    {
        int r0 = mw + (lane >> 2);
        int r1 = r0 + 8;
        float* d0 = &g_agg_s[(size_t)sdst[r0] * 128];
        float* d1 = &g_agg_s[(size_t)sdst[r1] * 128];
        bool v0 = (r0 < nval), v1 = (r1 < nval);
#pragma unroll
        for (int nt = 0; nt < 8; ++nt) {
            int n = nw + nt * 8 + (lane & 3) * 2;
            float2 bb = *(const float2*)&b2[n];
            if (v0) red2(d0 + n, acc[nt][0] + bb.x, acc[nt][1] + bb.y);
            if (v1) red2(d1 + n, acc[nt][2] + bb.x, acc[nt][3] + bb.y);
        }
        if (wid < 4) {
#pragma unroll
            for (int gn = 0; gn < 2; ++gn) {
                int col = gn * 8 + (lane & 3) * 2;
                float b0 = g_bgp[col], b1g = g_bgp[col + 1];
                sg[r0 * 16 + col]     = sigmoidf_(gacc[gn][0] + b0);
                sg[r0 * 16 + col + 1] = sigmoidf_(gacc[gn][1] + b1g);
                sg[r1 * 16 + col]     = sigmoidf_(gacc[gn][2] + b0);
                sg[r1 * 16 + col + 1] = sigmoidf_(gacc[gn][3] + b1g);
            }
        }
    }
    __syncthreads();

    // ---- v projection via precomputed VA/VB, scatter-add ----
    for (int q = tid; q < BE * 12; q += 256) {
        int e = q / 12, rq = q - e * 12;
        if (e >= nval) continue;
        float4 a4 = *(const float4*)&g_VA[(size_t)ssrc[e] * 48 + rq * 4];
        float4 b4 = *(const float4*)&g_VB[(size_t)sdst[e] * 48 + rq * 4];
        float av[4] = {a4.x + b4.x, a4.y + b4.y, a4.z + b4.z, a4.w + b4.w};
        float out[4];
#pragma unroll
        for (int u = 0; u < 4; ++u) {
            int r = rq * 4 + u, w = r / 3, c3 = r - w * 3;
            float val = av[u] + smf[OB_SEV / 4 + e * 4 + c3] * smf[OB_WV32 / 4 + w];
            out[u] = val * sg[e * 16 + w];
        }
        red4(&g_agg_v[(size_t)sdst[e] * 48 + rq * 4], out[0], out[1], out[2], out[3]);
    }
}

// ---------------------------------------------------------------------------
// Node update kernel (r12, verified)
// ---------------------------------------------------------------------------
__global__ __launch_bounds__(128) void node_kernel(
    const float* __restrict__ s, const float* __restrict__ v,
    const float* __restrict__ W1, const float* __restrict__ b1,
    const float* __restrict__ W2, const float* __restrict__ b2,
    const float* __restrict__ Wv, const float* __restrict__ Wg,
    const float* __restrict__ bg, const float* __restrict__ lng,
    const float* __restrict__ lnb,
    float* __restrict__ out_s, float* __restrict__ out_v, int n)
{
    __shared__ float xu[8][164];
    __shared__ float vinB[8][48];
    __shared__ float tt[8][128];
    __shared__ float dsm[8][132];
    __shared__ float gate[8][16];
    __shared__ float rsum[8][4], rsq[8][4];

    const int tid = threadIdx.x;
    const int n0 = blockIdx.x * 8;

    for (int idx = tid; idx < 8 * 144; idx += 128) {
        int i = idx / 144, k = idx - i * 144;
        int nd = min(n0 + i, n - 1);
        xu[i][k] = (k < 128) ? g_agg_s[(size_t)nd * 128 + k]
                             : g_vn[(size_t)nd * 16 + (k - 128)];
    }
    for (int idx = tid; idx < 8 * 48; idx += 128) {
        int i = idx / 48, k = idx - i * 48;
        int nd = min(n0 + i, n - 1);
        vinB[i][k] = g_agg_v[(size_t)nd * 48 + k];
    }
    __syncthreads();
    for (int idx = tid; idx < 8 * 16; idx += 128) {
        int i = idx >> 4, j = idx & 15;
        float a = vinB[i][j * 3], b = vinB[i][j * 3 + 1], c = vinB[i][j * 3 + 2];
        xu[i][144 + j] = sqrtf(fmaxf(a * a + b * b + c * c, 1e-8f));
    }
    __syncthreads();

    const int c = tid;
    float acc[8];
    {
        float bb = b1[c];
#pragma unroll
        for (int i = 0; i < 8; ++i) {
            int nd = min(n0 + i, n - 1);
            acc[i] = g_Z[(size_t)nd * 128 + c] + bb;
        }
    }
    for (int k = 0; k < 160; ++k) {
        float w = W1[(128 + k) * 128 + c];
#pragma unroll
        for (int i = 0; i < 8; ++i) acc[i] = fmaf(xu[i][k], w, acc[i]);
    }
#pragma unroll
    for (int i = 0; i < 8; ++i) {
        float h = acc[i];
        tt[i][c] = h * sigmoidf_(h);
    }
    __syncthreads();

    float acc2[8];
    {
        float bb = b2[c];
#pragma unroll
        for (int i = 0; i < 8; ++i) acc2[i] = bb;
    }
    for (int k = 0; k < 128; ++k) {
        float w = W2[k * 128 + c];
#pragma unroll
        for (int i = 0; i < 8; ++i) acc2[i] = fmaf(tt[i][k], w, acc2[i]);
    }
#pragma unroll
    for (int i = 0; i < 8; ++i) dsm[i][c] = acc2[i];
    __syncthreads();

    {
        int i = tid >> 4, w = tid & 15;
        float g = bg[w];
        for (int cc = 0; cc < 128; ++cc)
            g = fmaf(dsm[i][cc], Wg[cc * 16 + w], g);
        gate[i][w] = sigmoidf_(g);
    }

    float val[8];
#pragma unroll
    for (int i = 0; i < 8; ++i) {
        int nd = min(n0 + i, n - 1);
        val[i] = s[nd * 128 + c] + acc2[i];
    }
    const int lane = tid & 31, wq = tid >> 5;
    float psum[8], psq[8];
#pragma unroll
    for (int i = 0; i < 8; ++i) { psum[i] = val[i]; psq[i] = val[i] * val[i]; }
#pragma unroll
    for (int off = 16; off > 0; off >>= 1) {
#pragma unroll
        for (int i = 0; i < 8; ++i) {
            psum[i] += __shfl_xor_sync(0xffffffffu, psum[i], off);
            psq[i]  += __shfl_xor_sync(0xffffffffu, psq[i],  off);
        }
    }
    if (lane == 0) {
#pragma unroll
        for (int i = 0; i < 8; ++i) { rsum[i][wq] = psum[i]; rsq[i][wq] = psq[i]; }
    }
    __syncthreads();

#pragma unroll
    for (int i = 0; i < 8; ++i) {
        if (n0 + i >= n) continue;
        float sum = rsum[i][0] + rsum[i][1] + rsum[i][2] + rsum[i][3];
        float sq  = rsq[i][0] + rsq[i][1] + rsq[i][2] + rsq[i][3];
        float mu  = sum * (1.0f / 128.0f);
        float var = sq * (1.0f / 128.0f) - mu * mu;
        float o = (val[i] - mu) * rsqrtf(var + 1e-5f) * lng[c] + lnb[c];
        out_s[(n0 + i) * 128 + c] = o;
    }

    for (int q = tid; q < 8 * 48; q += 128) {
        int i = q / 48, r = q - i * 48;
        if (n0 + i >= n) continue;
        int w = r / 3, cc = r - w * 3;
        float a = g_UVA[(size_t)(n0 + i) * 48 + r];
#pragma unroll
        for (int j = 0; j < 16; ++j)
            a = fmaf(vinB[i][j * 3 + cc], Wv[(16 + j) * 16 + w], a);
        a *= gate[i][w];
        out_v[(n0 + i) * 48 + r] = v[(n0 + i) * 48 + r] + a;
    }
}

// ---------------------------------------------------------------------------
extern "C" void kernel_launch(void* const* d_in, const int* in_sizes, int n_in,
                              void* d_out, int out_size)
{
    const float* s   = (const float*)d_in[0];
    const float* v   = (const float*)d_in[1];
    const int*   ei  = (const int*)  d_in[2];
    const float* es  = (const float*)d_in[3];
    const float* ev  = (const float*)d_in[4];
    const float* mW1 = (const float*)d_in[5];
    const float* mb1 = (const float*)d_in[6];
    const float* mW2 = (const float*)d_in[7];
    const float* mb2 = (const float*)d_in[8];
    const float* mWv = (const float*)d_in[9];
    const float* mWg = (const float*)d_in[10];
    const float* mbg = (const float*)d_in[11];
    const float* uW1 = (const float*)d_in[12];
    const float* ub1 = (const float*)d_in[13];
    const float* uW2 = (const float*)d_in[14];
    const float* ub2 = (const float*)d_in[15];
    const float* uWv = (const float*)d_in[16];
    const float* uWg = (const float*)d_in[17];
    const float* ubg = (const float*)d_in[18];
    const float* lng = (const float*)d_in[19];
    const float* lnb = (const float*)d_in[20];

    const int n = in_sizes[0] / 128;
    const int E = in_sizes[2] / 2;

    float* out_s = (float*)d_out;
    float* out_v = out_s + (size_t)n * 128;

    cudaFuncSetAttribute(edge_kernel,
                         cudaFuncAttributeMaxDynamicSharedMemorySize,
                         EDGE_SMEM_BYTES);

    zero_kernel<<<(n * 176 + 255) / 256, 256>>>(n);
    prep_weights<<<(77840 + 255) / 256, 256>>>(mW1, mW2, mb2, mWg, mbg, uW1);
    prep_nodes<<<(n + 31) / 32, 256>>>(v, mWv, uWv, n);
    y_kernel<<<dim3((n + 63) / 64, 3), 256>>>(s, n);

    edge_kernel<<<(E + BE - 1) / BE, 256, EDGE_SMEM_BYTES>>>(
        ei, es, ev, mb1, mb2, mWv, E);

    node_kernel<<<(n + 7) / 8, 128>>>(
        s, v, uW1, ub1, uW2, ub2, uWv, uWg, ubg, lng, lnb,
        out_s, out_v, n);
}